// round 14
// baseline (speedup 1.0000x reference)
#include <cuda_runtime.h>
#include <math.h>

#ifndef M_PI
#define M_PI 3.14159265358979323846
#endif

#define N_TOT   8388608
#define W       882
#define WP      884
#define NB      9510
#define REM     788
#define MCH     64
#define NCH     149
#define LASTS   38
#define GLEN    19
#define NG      8
#define AOFF    860
#define FSZ     1756
#define SRATE   44100.0

// band-reject slab geometry (measured good)
#define LBQ     64
#define BQW     4
#define BQTH    128
#define SLAB    2080
#define SPB     8192
#define NBQB    1024

// comb_Bdirect geometry
#define QOUT    224
#define NCV     21
#define FB      4800          // 6-copy periodic extension
#define LIFT    4410          // 5*W

#define PREPB   46            // prep blocks at front of kernel A

// ---- scratch ----
__device__ float  g_wt[W];
__device__ float  g_dstate[NCH * WP];
__device__ float  g_vstart[NCH * WP];
__device__ float  g_sA[NG * WP];         // row1 = X_1, rows 2..7 = Z_1..Z_6
__device__ float  g_cv[NCV * WP];        // conv partials
__device__ float  g_ks[N_TOT];
__device__ float2 g_blk[NBQB];
__device__ float2 g_blkP[NBQB];
__device__ float  g_MsF[18][4];          // M^(64 * 2^s), s=0..17
__device__ float  g_par[12];             // 0:d2 1:fa2 2..6:bq 7:ia 8:ir 9:sg 10:P 11:Q
__device__ float  g_Kt[GLEN * 256];      // reversed folded taps S^(64k), k=1..19
__device__ float  g_KtB[6 * 512];        // reversed UNfolded taps S^(64*19m), m=1..6
__device__ int    g_Kwk[GLEN + 1], g_Koff[GLEN + 1];
__device__ int    g_KBwk[6], g_KBc0[6];
__device__ unsigned g_bar;

// ---- grid barrier (comb kernel only; 84 blocks) ----
__device__ __forceinline__ void gbar(unsigned target) {
    __threadfence();
    __syncthreads();
    if (threadIdx.x == 0) {
        atomicAdd(&g_bar, 1u);
        while (*(volatile unsigned*)&g_bar < target) { }
    }
    __syncthreads();
    __threadfence();
}

// kernel geometry for S^(64k), window folded mod W
__device__ __forceinline__ void kgeom2(int k, int& c0e, int& wk, int& jb) {
    int m = 64 * k;
    int hw = (int)ceil(21.0 * sqrt((double)k));
    int c0 = m / 2 - hw;
    wk = (2 * hw + 4) & ~3;
    int red = (c0 / W) * W;
    int ce = c0 - red;
    ce -= (ce + wk - 1) & 3;      // force (ce+wk) % 4 == 1
    c0e = ce;
    jb = ce + red;
}

// unfolded geometry for comb_Bdirect kernels, k = 19*(m+1)
__device__ __forceinline__ void kgeomB(int k, int& c0a, int& wk) {
    int m = 64 * k;
    int hw = (int)ceil(21.0 * sqrt((double)k));
    c0a = m / 2 - hw;
    wk = (2 * hw + 4) & ~3;
}

__device__ __forceinline__ float ftanh2(float x2) {   // x2 = 2*x
    float e = __expf(x2);
    return __fdividef(e - 1.0f, e + 1.0f);
}

__device__ __forceinline__ void mload(int s, float& A, float& B, float& C, float& D) {
    A = g_MsF[s][0]; B = g_MsF[s][1]; C = g_MsF[s][2]; D = g_MsF[s][3];
}
__device__ __forceinline__ void mpow64(int e, float& ra, float& rb, float& rc, float& rd) {
    ra = 1.f; rb = 0.f; rc = 0.f; rd = 1.f;
    for (int s = 0; e; s++, e >>= 1) {
        if (e & 1) {
            float A, B, C, D; mload(s, A, B, C, D);
            float na = A * ra + B * rc, nb = A * rb + B * rd;
            float nc = C * ra + D * rc, nd = C * rb + D * rd;
            ra = na; rb = nb; rc = nc; rd = nd;
        }
    }
}

// f[] circular extension: f[t] = v[(t - AOFF) mod W]
__device__ __forceinline__ void f_write(float* f, int p, float v) {
    f[p + AOFF] = v;
    if (p >= W - AOFF) f[p - (W - AOFF)] = v;
    if (p < FSZ - (W + AOFF)) f[p + W + AOFF] = v;
}

__device__ __forceinline__ void conv_into(const float* __restrict__ f,
                                          const float* __restrict__ Ks,
                                          int wk, int off, int o0, float* acc) {
    int b0 = o0 + off;
    float4 da = *(const float4*)&f[b0];
    #pragma unroll 2
    for (int jj = 0; jj < wk; jj += 4) {
        float4 ka = *(const float4*)&Ks[jj];
        float4 db = *(const float4*)&f[b0 + jj + 4];
        acc[0] = fmaf(ka.x, da.x, acc[0]); acc[0] = fmaf(ka.y, da.y, acc[0]);
        acc[0] = fmaf(ka.z, da.z, acc[0]); acc[0] = fmaf(ka.w, da.w, acc[0]);
        acc[1] = fmaf(ka.x, da.y, acc[1]); acc[1] = fmaf(ka.y, da.z, acc[1]);
        acc[1] = fmaf(ka.z, da.w, acc[1]); acc[1] = fmaf(ka.w, db.x, acc[1]);
        acc[2] = fmaf(ka.x, da.z, acc[2]); acc[2] = fmaf(ka.y, da.w, acc[2]);
        acc[2] = fmaf(ka.z, db.x, acc[2]); acc[2] = fmaf(ka.w, db.y, acc[2]);
        acc[3] = fmaf(ka.x, da.w, acc[3]); acc[3] = fmaf(ka.y, db.x, acc[3]);
        acc[3] = fmaf(ka.z, db.y, acc[3]); acc[3] = fmaf(ka.w, db.z, acc[3]);
        da = db;
    }
}

// X_g assembled from Z_{g-1} + conv partials (fixed order = deterministic)
__device__ __forceinline__ float xval(int g, int p) {
    if (g == 1) return g_sA[WP + p];
    float v = g_sA[(size_t)g * WP + p];              // Z_{g-1}
    int base = (g - 2) * (g - 1) / 2;
    #pragma unroll 6
    for (int m = 0; m < 6; m++)
        if (m < g - 1) v += g_cv[(size_t)(base + m) * WP + p];
    return v;
}

// ============================================================
// Karplus runner: 2 steps per barrier round.
// ============================================================
template<int NR, bool P1>
__device__ __forceinline__ void ks_run2(const float* __restrict__ xin,
                                        float* __restrict__ uout,
                                        float* __restrict__ op,
                                        float& a,
                                        float (*bsh)[W], float (*ush)[W],
                                        bool act, int i, int im1, int im2,
                                        float d2, float fa2) {
    float xa[2], xb[2];
    #pragma unroll
    for (int q = 0; q < 2; q++) {
        xa[q] = act ? xin[(size_t)(2 * q) * W] : 0.f;
        xb[q] = act ? xin[(size_t)(2 * q + 1) * W] : 0.f;
    }
    #pragma unroll 2
    for (int r = 0; r < NR; r++) {
        float x0 = xa[r & 1], x1 = xb[r & 1];
        if (act && r + 2 < NR) {
            xa[r & 1] = xin[(size_t)(2 * r + 4) * W];
            xb[r & 1] = xin[(size_t)(2 * r + 5) * W];
        }
        float u0, u1;
        if (P1) {
            u0 = ftanh2(fa2 * x0);
            u1 = ftanh2(fa2 * x1);
            if (act) {
                uout[(size_t)(2 * r) * W] = u0;
                uout[(size_t)(2 * r + 1) * W] = u1;
            }
        } else { u0 = x0; u1 = x1; }

        float bb = a + u0;
        if (act) { bsh[r & 1][i] = bb; ush[r & 1][i] = u1; }
        __syncthreads();
        if (act) {
            float bm1 = bsh[r & 1][im1], bm2 = bsh[r & 1][im2];
            float u1m1 = ush[r & 1][im1];
            float a1  = d2 * (bb + bm1);
            float a1m = d2 * (bm1 + bm2);
            float a2  = d2 * ((a1 + u1) + (a1m + u1m1));
            if (!P1) {
                op[(size_t)(2 * r) * W] = a1;
                op[(size_t)(2 * r + 1) * W] = a2;
            }
            a = a2;
        }
    }
}

// ============================================================
// Kernel A <<<195,896>>>: prep (blocks 0..45) + pass1 (46..194)
// ============================================================
struct SmemKS { float bsh[2][W]; float ush[2][W]; };
struct SmemWT { float xs[898]; float ys[898]; float2 sv[128]; float Pw[7][4]; float cf[10]; };

__global__ void __launch_bounds__(896) ksA(const float* __restrict__ fb,
                                           float* __restrict__ uscr,
                                           const float* __restrict__ wavetable,
                                           const float* __restrict__ h,
                                           const float* __restrict__ envp,
                                           const float* __restrict__ lp2) {
    __shared__ union { SmemKS ks; SmemWT wt; } sm;
    int b = blockIdx.x, t = threadIdx.x;

    if (b >= PREPB) {
        // ---------------- pass1: zero-init chunk + tanh precompute
        int c = b - PREPB;
        int i = t;
        bool act = i < W;
        int im1 = (i == 0) ? (W - 1) : (i - 1);
        int im2 = (i <= 1) ? (i + W - 2) : (i - 2);
        float dec = fminf(fmaxf(h[0] * 0.1f + 0.9f, 0.9f), 0.999f);
        float d2 = dec * 0.5f;
        float fa2 = 2.0f * h[3];

        float a = 0.0f;
        const float* fp = fb   + (size_t)c * MCH * W + i;
        float*       up = uscr + (size_t)c * MCH * W + i;
        if (c < NCH - 1) {
            ks_run2<MCH / 2, true>(fp, up, nullptr, a, sm.ks.bsh, sm.ks.ush,
                                   act, i, im1, im2, d2, fa2);
            if (act) g_dstate[c * WP + i] = a;
        } else {
            ks_run2<LASTS / 2, true>(fp, up, nullptr, a, sm.ks.bsh, sm.ks.ush,
                                     act, i, im1, im2, d2, fa2);
        }
        return;
    }

    if (b >= 40) {
        // KB table rows (6 x 512 unfolded taps), t<128 active
        if (t < 128) {
            int idx = (b - 40) * 128 + t;
            double decay = (double)h[0] / 10.0 + 0.9;
            decay = fmin(fmax(decay, 0.9), 0.999);
            double ld2 = log(decay * 0.5);
            int m = idx / 512;
            int jj = idx % 512;
            int k = 19 * (m + 1);
            int c0a, wk; kgeomB(k, c0a, wk);
            int m64 = 64 * k;
            float val = 0.0f;
            if (jj < wk) {
                int j = c0a + wk - 1 - jj;
                if (j >= 0 && j <= m64) {
                    double lg = lgamma((double)(m64 + 1)) - lgamma((double)(j + 1))
                              - lgamma((double)(m64 - j + 1)) + (double)m64 * ld2;
                    val = (float)exp(lg);
                }
            }
            g_KtB[idx] = val;
        }
        return;
    }

    if (b >= 2) {
        // K table rows k=1..19, t<128 active
        if (t < 128) {
            int idx = (b - 2) * 128 + t;        // 38*128 = 4864
            double decay = (double)h[0] / 10.0 + 0.9;
            decay = fmin(fmax(decay, 0.9), 0.999);
            double ld2 = log(decay * 0.5);
            int k = idx / 256 + 1;
            int jj = idx % 256;
            int c0e, wk, jb; kgeom2(k, c0e, wk, jb);
            int m = 64 * k;
            float val = 0.0f;
            if (jj < wk) {
                int j = jb + wk - 1 - jj;
                if (j >= 0 && j <= m) {
                    double lg = lgamma((double)(m + 1)) - lgamma((double)(j + 1))
                              - lgamma((double)(m - j + 1)) + (double)m * ld2;
                    val = (float)exp(lg);
                }
            }
            g_Kt[idx] = val;
        }
        return;
    }

    if (b == 0) {
        // ---- scalars ----
        if (t >= 1 && t <= GLEN) {
            int c0e, wk, jb; kgeom2(t, c0e, wk, jb);
            g_Kwk[t] = wk;
            g_Koff[t] = AOFF + 1 - c0e - wk;
        }
        if (t >= 22 && t < 28) {
            int m = t - 22;
            int c0a, wk; kgeomB(19 * (m + 1), c0a, wk);
            g_KBwk[m] = wk;
            g_KBc0[m] = c0a;
        }
        if (t != 0) return;

        g_bar = 0;

        double decay = (double)h[0] / 10.0 + 0.9;
        decay = fmin(fmax(decay, 0.9), 0.999);

        double h5 = h[5], h6 = h[6];
        double brf = h5 * SRATE / 4.0; brf = fmin(fmax(brf, 100.0), SRATE / 2.0 - 1.0);
        double brq = fmin(fmax(h6, 0.1), 0.999);
        double w0b = 2.0 * M_PI * brf / SRATE, alb = sin(w0b) / (2.0 * brq), cwb = cos(w0b);
        double a0b = 1.0 + alb;
        double bb0 = 1.0 / a0b, bb1 = (-2.0 * cwb) / a0b;
        double ba1 = (-2.0 * cwb) / a0b, ba2 = (1.0 - alb) / a0b;

        {
            double m00 = -ba1, m01 = -ba2, m10 = 1.0, m11 = 0.0;
            for (int s = 0; s < 6; s++) {                    // -> M^64
                double n00 = m00 * m00 + m01 * m10, n01 = m00 * m01 + m01 * m11;
                double n10 = m10 * m00 + m11 * m10, n11 = m10 * m01 + m11 * m11;
                m00 = n00; m01 = n01; m10 = n10; m11 = n11;
            }
            for (int s = 0; s < 18; s++) {
                g_MsF[s][0] = (float)m00; g_MsF[s][1] = (float)m01;
                g_MsF[s][2] = (float)m10; g_MsF[s][3] = (float)m11;
                double n00 = m00 * m00 + m01 * m10, n01 = m00 * m01 + m01 * m11;
                double n10 = m10 * m00 + m11 * m10, n11 = m10 * m01 + m11 * m11;
                m00 = n00; m01 = n01; m10 = n10; m11 = n11;
            }
        }

        double nD = (double)N_TOT;
        double attack  = 1.0 + (double)envp[0] * 0.1 * nD;
        double release = 1.0 + (double)envp[2] * 0.1 * nD;
        double sustain = fmin(fmax((double)envp[1], 0.0), 1.0);

        g_par[0] = (float)(decay * 0.5);
        g_par[1] = (float)(2.0 * (double)h[3]);
        g_par[2] = (float)bb0; g_par[3] = (float)bb1; g_par[4] = (float)bb0;
        g_par[5] = (float)ba1; g_par[6] = (float)ba2;
        g_par[7] = (float)(1.0 / attack);
        g_par[8] = (float)(1.0 / release);
        g_par[9] = (float)(sustain * (double)h[4]);
        g_par[10] = (float)(ba1 * ba1 - ba2);   // P for 2-step expansion
        g_par[11] = (float)(ba1 * ba2);         // Q
        return;
    }

    // ---- b == 1: wavetable prefilter (t<128 active; barriers all-thread) ----
    {
        float* xs = sm.wt.xs; float* ys = sm.wt.ys;
        float2* sv = sm.wt.sv; float (*Pw)[4] = sm.wt.Pw; float* cf = sm.wt.cf;

        if (t < 128)
            for (int p = t; p < 896; p += 128) xs[2 + p] = (p < W) ? wavetable[p] : 0.0f;
        if (t < 2) { xs[t] = 0.0f; ys[t] = 0.0f; }

        if (t == 0) {
            double h1 = h[1], h2 = h[2];
            double lpf = h1 * SRATE / 4.0; lpf = fmin(fmax(lpf, 100.0), SRATE / 2.0 - 1.0);
            double lpq = fmin(fmax(h2, 0.1), 0.999);
            double w0 = 2.0 * M_PI * lpf / SRATE, al = sin(w0) / (2.0 * lpq), cw = cos(w0);
            double a0 = 1.0 + al;
            cf[0] = (float)(((1.0 - cw) * 0.5) / a0);
            cf[1] = (float)((1.0 - cw) / a0);
            cf[2] = cf[0];
            cf[3] = (float)((-2.0 * cw) / a0);
            cf[4] = (float)((1.0 - al) / a0);
            double c2 = 100.0 + (double)lp2[0] * 8000.0;
            double w02 = 2.0 * M_PI * c2 / SRATE, al2 = sin(w02) / (2.0 * 0.707), cw2 = cos(w02);
            double a02 = 1.0 + al2;
            cf[5] = (float)(((1.0 - cw2) * 0.5) / a02);
            cf[6] = (float)((1.0 - cw2) / a02);
            cf[7] = cf[5];
            cf[8] = (float)((-2.0 * cw2) / a02);
            cf[9] = (float)((1.0 - al2) / a02);
        }
        __syncthreads();

        #pragma unroll
        for (int f = 0; f < 2; f++) {
            float b0 = cf[5 * f + 0], b1 = cf[5 * f + 1], b2 = cf[5 * f + 2];
            float a1 = cf[5 * f + 3], a2 = cf[5 * f + 4];
            const float* in = (f == 0) ? xs : ys;
            int base = 2 + 7 * (t & 127);

            if (t < 128) {
                float y1 = 0.f, y2 = 0.f;
                #pragma unroll
                for (int i = 0; i < 7; i++) {
                    float cn = b0 * in[base + i] + b1 * in[base + i - 1] + b2 * in[base + i - 2];
                    float yn = cn - a1 * y1 - a2 * y2;
                    y2 = y1; y1 = yn;
                }
                sv[t] = make_float2(y1, y2);
            }
            if (t == 0) {
                double A00 = -(double)a1, A01 = -(double)a2, A10 = 1.0, A11 = 0.0;
                double q00 = A00*A00 + A01*A10, q01 = A00*A01 + A01*A11;
                double q10 = A10*A00 + A11*A10, q11 = A10*A01 + A11*A11;
                double r00 = q00*q00 + q01*q10, r01 = q00*q01 + q01*q11;
                double r10 = q10*q00 + q11*q10, r11 = q10*q01 + q11*q11;
                double s00 = r00*q00 + r01*q10, s01 = r00*q01 + r01*q11;
                double s10 = r10*q00 + r11*q10, s11 = r10*q01 + r11*q11;
                double m00 = s00*A00 + s01*A10, m01 = s00*A01 + s01*A11;
                double m10 = s10*A00 + s11*A10, m11 = s10*A01 + s11*A11;
                for (int s = 0; s < 7; s++) {
                    Pw[s][0] = (float)m00; Pw[s][1] = (float)m01;
                    Pw[s][2] = (float)m10; Pw[s][3] = (float)m11;
                    double n00 = m00*m00 + m01*m10, n01 = m00*m01 + m01*m11;
                    double n10 = m10*m00 + m11*m10, n11 = m10*m01 + m11*m11;
                    m00 = n00; m01 = n01; m10 = n10; m11 = n11;
                }
            }
            __syncthreads();

            for (int s = 0; s < 7; s++) {
                int off = 1 << s;
                float ax = 0.f, ay = 0.f;
                if (t < 128 && t >= off) {
                    float2 src = sv[t - off];
                    ax = Pw[s][0] * src.x + Pw[s][1] * src.y;
                    ay = Pw[s][2] * src.x + Pw[s][3] * src.y;
                }
                __syncthreads();
                if (t < 128) { sv[t].x += ax; sv[t].y += ay; }
                __syncthreads();
            }

            if (t < 128) {
                float py1 = 0.f, py2 = 0.f;
                if (t > 0) { py1 = sv[t - 1].x; py2 = sv[t - 1].y; }
                #pragma unroll
                for (int i = 0; i < 7; i++) {
                    float cn = b0 * in[base + i] + b1 * in[base + i - 1] + b2 * in[base + i - 2];
                    float yn = cn - a1 * py1 - a2 * py2;
                    py2 = py1; py1 = yn;
                    if (f == 0) ys[base + i] = yn;
                    else { int g = 7 * t + i; if (g < W) g_wt[g] = yn; }
                }
            }
            __syncthreads();
        }
    }
}

// ============================================================
// Kernel B <<<84,256>>>: comb_A (blocks 0..7) + gbar + Bdirect
// ============================================================
__global__ void __launch_bounds__(256) ks_comb() {
    __shared__ union {
        struct { float f[FSZ]; float Ks[256]; } a;
        struct { float f[FB];  float Ks[512]; } b;
    } smc;
    int blk = blockIdx.x, t = threadIdx.x;

    // ---------------- phase 1: comb_A on blocks 0..7
    if (blk < NG) {
        float* f  = smc.a.f;
        float* Ks = smc.a.Ks;
        int g = blk;
        for (int p = t; p < g_Kwk[1]; p += 256) Ks[p] = g_Kt[p];
        int wk = g_Kwk[1], off = g_Koff[1];
        int c1 = g * GLEN;
        int len = (g == NG - 1) ? (NCH - (NG - 1) * GLEN) : GLEN;
        int cend  = c1 + len;
        int cendT = (g == NG - 1) ? (NCH - 1) : cend;

        int cbeg;
        if (g == 0) {
            for (int p = t; p < W; p += 256) {
                float v = g_wt[p];
                f_write(f, p, v);
                g_vstart[p] = v;
            }
            cbeg = 1;
        } else {
            for (int p = t; p < W; p += 256) {
                float v = g_dstate[c1 * WP + p];
                f_write(f, p, v);
                g_vstart[(c1 + 1) * WP + p] = v;
            }
            cbeg = c1 + 2;
        }
        __syncthreads();

        int o0 = t * 4;
        bool activ = o0 < W;
        float4 dv = make_float4(0.f, 0.f, 0.f, 0.f);
        if (activ) dv = *(const float4*)(g_dstate + (size_t)(cbeg - 1) * WP + o0);

        for (int c = cbeg; c <= cendT; c++) {
            float4 dnext = make_float4(0.f, 0.f, 0.f, 0.f);
            if (activ && c <= cendT - 1)
                dnext = *(const float4*)(g_dstate + (size_t)c * WP + o0);

            float acc[4] = {dv.x, dv.y, dv.z, dv.w};
            if (activ) conv_into(f, Ks, wk, off, o0, acc);
            __syncthreads();
            if (activ) {
                float* dst;
                if (c < cend) dst = g_vstart + (size_t)c * WP + o0;
                else dst = g_sA + (size_t)(g + 1) * WP + o0;   // X_1 (g=0) / Z_g
                #pragma unroll
                for (int e = 0; e < 4; e++) {
                    int p = o0 + e;
                    if (p < W) { f_write(f, p, acc[e]); dst[e] = acc[e]; }
                }
            }
            __syncthreads();
            dv = dnext;
        }
    }
    gbar(NCV * 4);

    // ---------------- phase 2: Bdirect on all 84 blocks
    {
        float* f  = smc.b.f;
        float* Ks = smc.b.Ks;
        int cid = blk >> 2, q = blk & 3;

        int g = 2;
        #pragma unroll
        for (int gg = 3; gg <= 7; gg++)
            if (cid >= (gg - 2) * (gg - 1) / 2) g = gg;
        int m = cid - (g - 2) * (g - 1) / 2;
        int srcRow = g - m - 1;

        int wk = g_KBwk[m], c0a = g_KBc0[m];
        for (int p = t; p < wk; p += 256) Ks[p] = g_KtB[m * 512 + p];

        for (int p = t; p < W; p += 256) {
            float v = __ldcg(g_sA + (size_t)srcRow * WP + p);
            #pragma unroll
            for (int n = 0; n < 6; n++) {
                int tt = p + n * W;
                if (tt < FB) f[tt] = v;
            }
        }
        __syncthreads();

        int o = q * QOUT + t;
        if (t < QOUT && o < W) {
            float acc = 0.f;
            int base = o - c0a - wk + 1 + LIFT;
            #pragma unroll 4
            for (int jj = 0; jj < wk; jj += 4) {
                float4 k4 = *(const float4*)&Ks[jj];
                acc = fmaf(k4.x, f[base + jj],     acc);
                acc = fmaf(k4.y, f[base + jj + 1], acc);
                acc = fmaf(k4.z, f[base + jj + 2], acc);
                acc = fmaf(k4.w, f[base + jj + 3], acc);
            }
            g_cv[(size_t)cid * WP + o] = acc;
        }
    }
}

// ============================================================
// Kernel C <<<149,896>>>: pass2 with comb_C correction prologue
// ============================================================
__global__ void __launch_bounds__(896) ksC(const float* __restrict__ uscr) {
    __shared__ SmemKS sm;
    __shared__ __align__(16) float f[FSZ];
    __shared__ __align__(16) float Ks[256];
    int c = blockIdx.x, i = threadIdx.x;
    bool act = i < W;
    int im1 = (i == 0) ? (W - 1) : (i - 1);
    int im2 = (i <= 1) ? (i + W - 2) : (i - 2);
    float d2 = g_par[0];

    float a;
    if (c < GLEN) {
        a = act ? g_vstart[(size_t)c * WP + i] : 0.0f;
        __syncthreads();
    } else {
        int g = c / GLEN, r = c - g * GLEN;
        for (int p = i; p < W; p += 896) f_write(f, p, xval(g, p));
        int wk = 0, off = 0;
        if (r > 0) {
            wk = g_Kwk[r]; off = g_Koff[r];
            if (i < wk) Ks[i] = g_Kt[(r - 1) * 256 + i];
        }
        __syncthreads();
        if (r == 0) {
            a = act ? f[i + AOFF] : 0.0f;        // X_g directly
        } else {
            int o0 = i * 4;
            if (o0 < W) {
                const float* vp = g_vstart + (size_t)c * WP + o0;
                float acc[4] = {vp[0], vp[1], vp[2], vp[3]};
                conv_into(f, Ks, wk, off, o0, acc);
                #pragma unroll
                for (int e = 0; e < 4; e++)
                    if (o0 + e < W) sm.ush[0][o0 + e] = acc[e];
            }
            __syncthreads();
            a = act ? sm.ush[0][i] : 0.0f;
            __syncthreads();
        }
    }

    const float* up = uscr + (size_t)c * MCH * W + i;
    float*       op = g_ks + (size_t)c * MCH * W + i;

    if (c < NCH - 1) {
        ks_run2<MCH / 2, false>(up, nullptr, op, a, sm.bsh, sm.ush, act, i, im1, im2, d2, 0.f);
    } else {
        ks_run2<LASTS / 2, false>(up, nullptr, op, a, sm.bsh, sm.ush, act, i, im1, im2, d2, 0.f);
        __syncthreads();
        if (act) sm.bsh[0][i] = a;
        __syncthreads();
        if (i < REM) {
            float fin = d2 * (sm.bsh[0][i] + sm.bsh[0][im1]);
            int g = NB * W + i;
            if (g >= N_TOT - 256) fin *= (float)(N_TOT - 1 - g) * (1.0f / 255.0f);
            g_ks[g] = fin;
        }
    }
}

// ============================================================
// Band-reject slab machinery; 2-sample-step recurrence
// ============================================================
__device__ __forceinline__ void bq_load_slab(float* sl, int sb, int w, int l) {
    const float4* gp = (const float4*)(g_ks + (size_t)sb * SPB + (size_t)w * 2048);
    #pragma unroll
    for (int i = 0; i < 16; i++) {
        float4 v = gp[i * 32 + l];
        int s4 = i * 128 + l * 4;
        int c = s4 >> 6, k = s4 & 63;
        float* q = sl + c * 65 + k;
        q[0] = v.x; q[1] = v.y; q[2] = v.z; q[3] = v.w;
    }
}

// zero-init chunk run (2-sample step) + in-warp KS scan
__device__ __forceinline__ float2 bq_zero_scan(const float* slab, int sb, int t,
                                               int w, int l,
                                               float b0, float b1, float b2,
                                               float a1, float a2,
                                               float Pc, float Qc,
                                               float& hx1, float& hx2) {
    if (t == 0) {
        size_t s0 = (size_t)sb * SPB;
        hx1 = sb ? g_ks[s0 - 1] : 0.f;
        hx2 = sb ? g_ks[s0 - 2] : 0.f;
    } else {
        int pw = (t - 1) >> 5, pl = (t - 1) & 31;
        const float* pv = slab + pw * SLAB + pl * 65;
        hx1 = pv[63]; hx2 = pv[62];
    }
    const float* cp = slab + w * SLAB + l * 65;
    float x1 = hx1, x2 = hx2, y1 = 0.f, y2 = 0.f;
    #pragma unroll
    for (int k = 0; k < 64; k += 2) {
        float xA = cp[k], xB = cp[k + 1];
        float cA = fmaf(b0, xA, fmaf(b1, x1, b2 * x2));
        float cB = fmaf(b0, xB, fmaf(b1, xA, b2 * x1));
        float yA = cA - fmaf(a1, y1, a2 * y2);
        float yB = fmaf(Pc, y1, fmaf(Qc, y2, cB - a1 * cA));
        x2 = xA; x1 = xB; y2 = yA; y1 = yB;
    }
    float2 v = make_float2(y1, y2);
    #pragma unroll
    for (int s = 0; s < 5; s++) {
        int off = 1 << s;
        float px = __shfl_up_sync(0xffffffffu, v.x, off);
        float py = __shfl_up_sync(0xffffffffu, v.y, off);
        if (l >= off) {
            float A, B, C, D; mload(s, A, B, C, D);
            v.x = fmaf(A, px, fmaf(B, py, v.x));
            v.y = fmaf(C, px, fmaf(D, py, v.y));
        }
    }
    return v;
}

__global__ void __launch_bounds__(BQTH) bq_passA() {
    __shared__ __align__(16) float slab[BQW * SLAB];
    __shared__ float2 wag[BQW];
    int sb = blockIdx.x, t = threadIdx.x, w = t >> 5, l = t & 31;
    float b0 = g_par[2], b1 = g_par[3], b2 = g_par[4], a1 = g_par[5], a2 = g_par[6];
    float Pc = g_par[10], Qc = g_par[11];

    bq_load_slab(slab + w * SLAB, sb, w, l);
    __syncthreads();

    float hx1, hx2;
    float2 v = bq_zero_scan(slab, sb, t, w, l, b0, b1, b2, a1, a2, Pc, Qc, hx1, hx2);
    if (l == 31) wag[w] = v;
    __syncthreads();

    if (t == BQTH - 1) {
        float A, B, C, D; mload(5, A, B, C, D);   // M^2048
        float2 P = wag[0];
        #pragma unroll
        for (int u = 1; u < BQW; u++) {
            float2 nw = wag[u];
            P = make_float2(nw.x + A * P.x + B * P.y, nw.y + C * P.x + D * P.y);
        }
        g_blk[sb] = P;
    }
}

__global__ void __launch_bounds__(1024) bq_scanK() {
    __shared__ float2 sv[NBQB];
    int t = threadIdx.x;
    sv[t] = g_blk[t];
    __syncthreads();
    for (int s = 0; s < 10; s++) {
        int off = 1 << s;
        float A, B, C, D; mload(7 + s, A, B, C, D);   // M^(8192*2^s)
        float ax = 0.f, ay = 0.f;
        if (t >= off) {
            float2 sr = sv[t - off];
            ax = fmaf(A, sr.x, B * sr.y);
            ay = fmaf(C, sr.x, D * sr.y);
        }
        __syncthreads();
        sv[t].x += ax; sv[t].y += ay;
        __syncthreads();
    }
    g_blkP[t] = t ? sv[t - 1] : make_float2(0.f, 0.f);
}

__global__ void __launch_bounds__(BQTH) bq_passB(float* __restrict__ out) {
    __shared__ __align__(16) float slab[BQW * SLAB];
    __shared__ float2 wag[BQW];
    int sb = blockIdx.x, t = threadIdx.x, w = t >> 5, l = t & 31;
    float b0 = g_par[2], b1 = g_par[3], b2 = g_par[4], a1 = g_par[5], a2 = g_par[6];
    float Pc = g_par[10], Qc = g_par[11];

    bq_load_slab(slab + w * SLAB, sb, w, l);
    __syncthreads();

    float hx1, hx2;
    float2 v = bq_zero_scan(slab, sb, t, w, l, b0, b1, b2, a1, a2, Pc, Qc, hx1, hx2);
    if (l == 31) wag[w] = v;
    __syncthreads();

    float2 P = make_float2(0.f, 0.f);
    {
        float A, B, C, D; mload(5, A, B, C, D);
        for (int u = 0; u < w; u++) {
            float2 nw = wag[u];
            P = make_float2(nw.x + A * P.x + B * P.y, nw.y + C * P.x + D * P.y);
        }
    }
    float ex = __shfl_up_sync(0xffffffffu, v.x, 1);
    float ey = __shfl_up_sync(0xffffffffu, v.y, 1);
    if (l == 0) { ex = 0.f; ey = 0.f; }
    {
        float ra, rb, rc, rd; mpow64(l, ra, rb, rc, rd);
        ex += ra * P.x + rb * P.y;
        ey += rc * P.x + rd * P.y;
    }
    {
        float2 Pb = g_blkP[sb];
        float ra, rb, rc, rd; mpow64(t, ra, rb, rc, rd);
        ex += ra * Pb.x + rb * Pb.y;
        ey += rc * Pb.x + rd * Pb.y;
    }

    // replay in-place with envelope (2-sample step)
    {
        float ia = g_par[7], ir = g_par[8], sg = g_par[9];
        float* cp = slab + w * SLAB + l * 65;
        float x1 = hx1, x2 = hx2, y1 = ex, y2 = ey;
        size_t s0 = (size_t)sb * SPB + (size_t)t * 64;
        #pragma unroll
        for (int k = 0; k < 64; k += 2) {
            float xA = cp[k], xB = cp[k + 1];
            float cA = fmaf(b0, xA, fmaf(b1, x1, b2 * x2));
            float cB = fmaf(b0, xB, fmaf(b1, xA, b2 * x1));
            float yA = cA - fmaf(a1, y1, a2 * y2);
            float yB = fmaf(Pc, y1, fmaf(Qc, y2, cB - a1 * cA));
            x2 = xA; x1 = xB; y2 = yA; y1 = yB;
            float fnA = (float)(s0 + k);
            float fnB = (float)(s0 + k + 1);
            float e1A = fminf(fnA * ia, 1.0f);
            float e2A = fminf(((float)(N_TOT - 1) - fnA) * ir, 1.0f);
            float e1B = fminf(fnB * ia, 1.0f);
            float e2B = fminf(((float)(N_TOT - 1) - fnB) * ir, 1.0f);
            cp[k]     = yA * e1A * e2A * sg;
            cp[k + 1] = yB * e1B * e2B * sg;
        }
    }
    __syncwarp();

    {
        const float* sl = slab + w * SLAB;
        float4* op = (float4*)(out + (size_t)sb * SPB + (size_t)w * 2048);
        #pragma unroll
        for (int i = 0; i < 16; i++) {
            int s4 = i * 128 + l * 4;
            int c = s4 >> 6, k = s4 & 63;
            const float* q = sl + c * 65 + k;
            op[i * 32 + l] = make_float4(q[0], q[1], q[2], q[3]);
        }
    }
}

// ============================================================
extern "C" void kernel_launch(void* const* d_in, const int* in_sizes, int n_in,
                              void* d_out, int out_size) {
    const float* fb  = (const float*)d_in[0];
    const float* wt  = (const float*)d_in[1];
    const float* h   = (const float*)d_in[2];
    const float* ep  = (const float*)d_in[3];
    const float* lp2 = (const float*)d_in[4];
    float* out = (float*)d_out;

    ksA<<<PREPB + NCH, 896>>>(fb, out, wt, h, ep, lp2);  // prep + pass1 (u -> out)
    ks_comb<<<NCV * 4, 256>>>();                          // comb_A + gbar + Bdirect
    ksC<<<NCH, 896>>>(out);                               // comb_C prologue + pass2
    bq_passA<<<NBQB, BQTH>>>();
    bq_scanK<<<1, 1024>>>();
    bq_passB<<<NBQB, BQTH>>>(out);
}

// round 15
// speedup vs baseline: 1.3979x; 1.3979x over previous
#include <cuda_runtime.h>
#include <math.h>

#ifndef M_PI
#define M_PI 3.14159265358979323846
#endif

#define N_TOT   8388608
#define W       882
#define WP      884
#define NB      9510
#define REM     788
#define MCH     64
#define NCH     149
#define LASTS   38
#define GLEN    19
#define NG      8
#define AOFF    860
#define FSZ     1756
#define SRATE   44100.0

// band-reject slab geometry (measured good)
#define LBQ     64
#define BQW     4
#define BQTH    128
#define SLAB    2080
#define SPB     8192
#define NBQB    1024

// comb_Bdirect geometry
#define QOUT    224
#define NCV     21
#define FB      4800          // 6-copy periodic extension
#define LIFT    4410          // 5*W

#define PREPB   46            // prep blocks at front of kernel A

// ---- scratch ----
__device__ float  g_wt[W];
__device__ float  g_dstate[NCH * WP];
__device__ float  g_vstart[NCH * WP];
__device__ float  g_sA[NG * WP];         // row1 = X_1, rows 2..7 = Z_1..Z_6
__device__ float  g_cv[NCV * WP];        // conv partials
__device__ float  g_ks[N_TOT];
__device__ float2 g_blk[NBQB];
__device__ float  g_MsF[18][4];          // M^(64 * 2^s), s=0..17
__device__ float  g_par[12];             // 0:d2 1:fa2 2..6:bq 7:ia 8:ir 9:sg
__device__ float  g_Kt[GLEN * 256];      // reversed folded taps S^(64k), k=1..19
__device__ float  g_KtB[6 * 512];        // reversed UNfolded taps S^(64*19m), m=1..6
__device__ int    g_Kwk[GLEN + 1], g_Koff[GLEN + 1];
__device__ int    g_KBwk[6], g_KBc0[6];
__device__ unsigned g_bar;

// ---- grid barrier (comb kernel only; 84 blocks) ----
__device__ __forceinline__ void gbar(unsigned target) {
    __threadfence();
    __syncthreads();
    if (threadIdx.x == 0) {
        atomicAdd(&g_bar, 1u);
        while (*(volatile unsigned*)&g_bar < target) { }
    }
    __syncthreads();
    __threadfence();
}

// kernel geometry for S^(64k), window folded mod W
__device__ __forceinline__ void kgeom2(int k, int& c0e, int& wk, int& jb) {
    int m = 64 * k;
    int hw = (int)ceil(21.0 * sqrt((double)k));
    int c0 = m / 2 - hw;
    wk = (2 * hw + 4) & ~3;
    int red = (c0 / W) * W;
    int ce = c0 - red;
    ce -= (ce + wk - 1) & 3;      // force (ce+wk) % 4 == 1
    c0e = ce;
    jb = ce + red;
}

// unfolded geometry for comb_Bdirect kernels, k = 19*(m+1)
__device__ __forceinline__ void kgeomB(int k, int& c0a, int& wk) {
    int m = 64 * k;
    int hw = (int)ceil(21.0 * sqrt((double)k));
    c0a = m / 2 - hw;
    wk = (2 * hw + 4) & ~3;
}

__device__ __forceinline__ float ftanh2(float x2) {   // x2 = 2*x
    float e = __expf(x2);
    return __fdividef(e - 1.0f, e + 1.0f);
}

__device__ __forceinline__ void mload(int s, float& A, float& B, float& C, float& D) {
    A = g_MsF[s][0]; B = g_MsF[s][1]; C = g_MsF[s][2]; D = g_MsF[s][3];
}
__device__ __forceinline__ void mpow64(int e, float& ra, float& rb, float& rc, float& rd) {
    ra = 1.f; rb = 0.f; rc = 0.f; rd = 1.f;
    for (int s = 0; e; s++, e >>= 1) {
        if (e & 1) {
            float A, B, C, D; mload(s, A, B, C, D);
            float na = A * ra + B * rc, nb = A * rb + B * rd;
            float nc = C * ra + D * rc, nd = C * rb + D * rd;
            ra = na; rb = nb; rc = nc; rd = nd;
        }
    }
}

// f[] circular extension: f[t] = v[(t - AOFF) mod W]
__device__ __forceinline__ void f_write(float* f, int p, float v) {
    f[p + AOFF] = v;
    if (p >= W - AOFF) f[p - (W - AOFF)] = v;
    if (p < FSZ - (W + AOFF)) f[p + W + AOFF] = v;
}

__device__ __forceinline__ void conv_into(const float* __restrict__ f,
                                          const float* __restrict__ Ks,
                                          int wk, int off, int o0, float* acc) {
    int b0 = o0 + off;
    float4 da = *(const float4*)&f[b0];
    #pragma unroll 2
    for (int jj = 0; jj < wk; jj += 4) {
        float4 ka = *(const float4*)&Ks[jj];
        float4 db = *(const float4*)&f[b0 + jj + 4];
        acc[0] = fmaf(ka.x, da.x, acc[0]); acc[0] = fmaf(ka.y, da.y, acc[0]);
        acc[0] = fmaf(ka.z, da.z, acc[0]); acc[0] = fmaf(ka.w, da.w, acc[0]);
        acc[1] = fmaf(ka.x, da.y, acc[1]); acc[1] = fmaf(ka.y, da.z, acc[1]);
        acc[1] = fmaf(ka.z, da.w, acc[1]); acc[1] = fmaf(ka.w, db.x, acc[1]);
        acc[2] = fmaf(ka.x, da.z, acc[2]); acc[2] = fmaf(ka.y, da.w, acc[2]);
        acc[2] = fmaf(ka.z, db.x, acc[2]); acc[2] = fmaf(ka.w, db.y, acc[2]);
        acc[3] = fmaf(ka.x, da.w, acc[3]); acc[3] = fmaf(ka.y, db.x, acc[3]);
        acc[3] = fmaf(ka.z, db.y, acc[3]); acc[3] = fmaf(ka.w, db.z, acc[3]);
        da = db;
    }
}

// X_g assembled from Z_{g-1} + conv partials (fixed order = deterministic)
__device__ __forceinline__ float xval(int g, int p) {
    if (g == 1) return g_sA[WP + p];
    float v = g_sA[(size_t)g * WP + p];              // Z_{g-1}
    int base = (g - 2) * (g - 1) / 2;
    #pragma unroll 6
    for (int m = 0; m < 6; m++)
        if (m < g - 1) v += g_cv[(size_t)(base + m) * WP + p];
    return v;
}

// ============================================================
// Karplus runner: 2 steps per barrier round.
// ============================================================
template<int NR, bool P1>
__device__ __forceinline__ void ks_run2(const float* __restrict__ xin,
                                        float* __restrict__ uout,
                                        float* __restrict__ op,
                                        float& a,
                                        float (*bsh)[W], float (*ush)[W],
                                        bool act, int i, int im1, int im2,
                                        float d2, float fa2) {
    float xa[2], xb[2];
    #pragma unroll
    for (int q = 0; q < 2; q++) {
        xa[q] = act ? xin[(size_t)(2 * q) * W] : 0.f;
        xb[q] = act ? xin[(size_t)(2 * q + 1) * W] : 0.f;
    }
    #pragma unroll 2
    for (int r = 0; r < NR; r++) {
        float x0 = xa[r & 1], x1 = xb[r & 1];
        if (act && r + 2 < NR) {
            xa[r & 1] = xin[(size_t)(2 * r + 4) * W];
            xb[r & 1] = xin[(size_t)(2 * r + 5) * W];
        }
        float u0, u1;
        if (P1) {
            u0 = ftanh2(fa2 * x0);
            u1 = ftanh2(fa2 * x1);
            if (act) {
                uout[(size_t)(2 * r) * W] = u0;
                uout[(size_t)(2 * r + 1) * W] = u1;
            }
        } else { u0 = x0; u1 = x1; }

        float bb = a + u0;
        if (act) { bsh[r & 1][i] = bb; ush[r & 1][i] = u1; }
        __syncthreads();
        if (act) {
            float bm1 = bsh[r & 1][im1], bm2 = bsh[r & 1][im2];
            float u1m1 = ush[r & 1][im1];
            float a1  = d2 * (bb + bm1);
            float a1m = d2 * (bm1 + bm2);
            float a2  = d2 * ((a1 + u1) + (a1m + u1m1));
            if (!P1) {
                op[(size_t)(2 * r) * W] = a1;
                op[(size_t)(2 * r + 1) * W] = a2;
            }
            a = a2;
        }
    }
}

// ============================================================
// Kernel A <<<195,896>>>: prep (blocks 0..45) + pass1 (46..194)
// ============================================================
struct SmemKS { float bsh[2][W]; float ush[2][W]; };
struct SmemWT { float xs[898]; float ys[898]; float2 sv[128]; float Pw[7][4]; float cf[10]; };

__global__ void __launch_bounds__(896) ksA(const float* __restrict__ fb,
                                           float* __restrict__ uscr,
                                           const float* __restrict__ wavetable,
                                           const float* __restrict__ h,
                                           const float* __restrict__ envp,
                                           const float* __restrict__ lp2) {
    __shared__ union { SmemKS ks; SmemWT wt; } sm;
    int b = blockIdx.x, t = threadIdx.x;

    if (b >= PREPB) {
        // ---------------- pass1: zero-init chunk + tanh precompute
        int c = b - PREPB;
        int i = t;
        bool act = i < W;
        int im1 = (i == 0) ? (W - 1) : (i - 1);
        int im2 = (i <= 1) ? (i + W - 2) : (i - 2);
        float dec = fminf(fmaxf(h[0] * 0.1f + 0.9f, 0.9f), 0.999f);
        float d2 = dec * 0.5f;
        float fa2 = 2.0f * h[3];

        float a = 0.0f;
        const float* fp = fb   + (size_t)c * MCH * W + i;
        float*       up = uscr + (size_t)c * MCH * W + i;
        if (c < NCH - 1) {
            ks_run2<MCH / 2, true>(fp, up, nullptr, a, sm.ks.bsh, sm.ks.ush,
                                   act, i, im1, im2, d2, fa2);
            if (act) g_dstate[c * WP + i] = a;
        } else {
            ks_run2<LASTS / 2, true>(fp, up, nullptr, a, sm.ks.bsh, sm.ks.ush,
                                     act, i, im1, im2, d2, fa2);
        }
        return;
    }

    if (b >= 40) {
        // KB table rows (6 x 512 unfolded taps), t<128 active
        if (t < 128) {
            int idx = (b - 40) * 128 + t;
            double decay = (double)h[0] / 10.0 + 0.9;
            decay = fmin(fmax(decay, 0.9), 0.999);
            double ld2 = log(decay * 0.5);
            int m = idx / 512;
            int jj = idx % 512;
            int k = 19 * (m + 1);
            int c0a, wk; kgeomB(k, c0a, wk);
            int m64 = 64 * k;
            float val = 0.0f;
            if (jj < wk) {
                int j = c0a + wk - 1 - jj;
                if (j >= 0 && j <= m64) {
                    double lg = lgamma((double)(m64 + 1)) - lgamma((double)(j + 1))
                              - lgamma((double)(m64 - j + 1)) + (double)m64 * ld2;
                    val = (float)exp(lg);
                }
            }
            g_KtB[idx] = val;
        }
        return;
    }

    if (b >= 2) {
        // K table rows k=1..19, t<128 active
        if (t < 128) {
            int idx = (b - 2) * 128 + t;        // 38*128 = 4864
            double decay = (double)h[0] / 10.0 + 0.9;
            decay = fmin(fmax(decay, 0.9), 0.999);
            double ld2 = log(decay * 0.5);
            int k = idx / 256 + 1;
            int jj = idx % 256;
            int c0e, wk, jb; kgeom2(k, c0e, wk, jb);
            int m = 64 * k;
            float val = 0.0f;
            if (jj < wk) {
                int j = jb + wk - 1 - jj;
                if (j >= 0 && j <= m) {
                    double lg = lgamma((double)(m + 1)) - lgamma((double)(j + 1))
                              - lgamma((double)(m - j + 1)) + (double)m * ld2;
                    val = (float)exp(lg);
                }
            }
            g_Kt[idx] = val;
        }
        return;
    }

    if (b == 0) {
        // ---- scalars ----
        if (t >= 1 && t <= GLEN) {
            int c0e, wk, jb; kgeom2(t, c0e, wk, jb);
            g_Kwk[t] = wk;
            g_Koff[t] = AOFF + 1 - c0e - wk;
        }
        if (t >= 22 && t < 28) {
            int m = t - 22;
            int c0a, wk; kgeomB(19 * (m + 1), c0a, wk);
            g_KBwk[m] = wk;
            g_KBc0[m] = c0a;
        }
        if (t != 0) return;

        g_bar = 0;

        double decay = (double)h[0] / 10.0 + 0.9;
        decay = fmin(fmax(decay, 0.9), 0.999);

        double h5 = h[5], h6 = h[6];
        double brf = h5 * SRATE / 4.0; brf = fmin(fmax(brf, 100.0), SRATE / 2.0 - 1.0);
        double brq = fmin(fmax(h6, 0.1), 0.999);
        double w0b = 2.0 * M_PI * brf / SRATE, alb = sin(w0b) / (2.0 * brq), cwb = cos(w0b);
        double a0b = 1.0 + alb;
        double bb0 = 1.0 / a0b, bb1 = (-2.0 * cwb) / a0b;
        double ba1 = (-2.0 * cwb) / a0b, ba2 = (1.0 - alb) / a0b;

        {
            double m00 = -ba1, m01 = -ba2, m10 = 1.0, m11 = 0.0;
            for (int s = 0; s < 6; s++) {                    // -> M^64
                double n00 = m00 * m00 + m01 * m10, n01 = m00 * m01 + m01 * m11;
                double n10 = m10 * m00 + m11 * m10, n11 = m10 * m01 + m11 * m11;
                m00 = n00; m01 = n01; m10 = n10; m11 = n11;
            }
            for (int s = 0; s < 18; s++) {
                g_MsF[s][0] = (float)m00; g_MsF[s][1] = (float)m01;
                g_MsF[s][2] = (float)m10; g_MsF[s][3] = (float)m11;
                double n00 = m00 * m00 + m01 * m10, n01 = m00 * m01 + m01 * m11;
                double n10 = m10 * m00 + m11 * m10, n11 = m10 * m01 + m11 * m11;
                m00 = n00; m01 = n01; m10 = n10; m11 = n11;
            }
        }

        double nD = (double)N_TOT;
        double attack  = 1.0 + (double)envp[0] * 0.1 * nD;
        double release = 1.0 + (double)envp[2] * 0.1 * nD;
        double sustain = fmin(fmax((double)envp[1], 0.0), 1.0);

        g_par[0] = (float)(decay * 0.5);
        g_par[1] = (float)(2.0 * (double)h[3]);
        g_par[2] = (float)bb0; g_par[3] = (float)bb1; g_par[4] = (float)bb0;
        g_par[5] = (float)ba1; g_par[6] = (float)ba2;
        g_par[7] = (float)(1.0 / attack);
        g_par[8] = (float)(1.0 / release);
        g_par[9] = (float)(sustain * (double)h[4]);
        return;
    }

    // ---- b == 1: wavetable prefilter (t<128 active; barriers all-thread) ----
    {
        float* xs = sm.wt.xs; float* ys = sm.wt.ys;
        float2* sv = sm.wt.sv; float (*Pw)[4] = sm.wt.Pw; float* cf = sm.wt.cf;

        if (t < 128)
            for (int p = t; p < 896; p += 128) xs[2 + p] = (p < W) ? wavetable[p] : 0.0f;
        if (t < 2) { xs[t] = 0.0f; ys[t] = 0.0f; }

        if (t == 0) {
            double h1 = h[1], h2 = h[2];
            double lpf = h1 * SRATE / 4.0; lpf = fmin(fmax(lpf, 100.0), SRATE / 2.0 - 1.0);
            double lpq = fmin(fmax(h2, 0.1), 0.999);
            double w0 = 2.0 * M_PI * lpf / SRATE, al = sin(w0) / (2.0 * lpq), cw = cos(w0);
            double a0 = 1.0 + al;
            cf[0] = (float)(((1.0 - cw) * 0.5) / a0);
            cf[1] = (float)((1.0 - cw) / a0);
            cf[2] = cf[0];
            cf[3] = (float)((-2.0 * cw) / a0);
            cf[4] = (float)((1.0 - al) / a0);
            double c2 = 100.0 + (double)lp2[0] * 8000.0;
            double w02 = 2.0 * M_PI * c2 / SRATE, al2 = sin(w02) / (2.0 * 0.707), cw2 = cos(w02);
            double a02 = 1.0 + al2;
            cf[5] = (float)(((1.0 - cw2) * 0.5) / a02);
            cf[6] = (float)((1.0 - cw2) / a02);
            cf[7] = cf[5];
            cf[8] = (float)((-2.0 * cw2) / a02);
            cf[9] = (float)((1.0 - al2) / a02);
        }
        __syncthreads();

        #pragma unroll
        for (int f = 0; f < 2; f++) {
            float b0 = cf[5 * f + 0], b1 = cf[5 * f + 1], b2 = cf[5 * f + 2];
            float a1 = cf[5 * f + 3], a2 = cf[5 * f + 4];
            const float* in = (f == 0) ? xs : ys;
            int base = 2 + 7 * (t & 127);

            if (t < 128) {
                float y1 = 0.f, y2 = 0.f;
                #pragma unroll
                for (int i = 0; i < 7; i++) {
                    float cn = b0 * in[base + i] + b1 * in[base + i - 1] + b2 * in[base + i - 2];
                    float yn = cn - a1 * y1 - a2 * y2;
                    y2 = y1; y1 = yn;
                }
                sv[t] = make_float2(y1, y2);
            }
            if (t == 0) {
                double A00 = -(double)a1, A01 = -(double)a2, A10 = 1.0, A11 = 0.0;
                double q00 = A00*A00 + A01*A10, q01 = A00*A01 + A01*A11;
                double q10 = A10*A00 + A11*A10, q11 = A10*A01 + A11*A11;
                double r00 = q00*q00 + q01*q10, r01 = q00*q01 + q01*q11;
                double r10 = q10*q00 + q11*q10, r11 = q10*q01 + q11*q11;
                double s00 = r00*q00 + r01*q10, s01 = r00*q01 + r01*q11;
                double s10 = r10*q00 + r11*q10, s11 = r10*q01 + r11*q11;
                double m00 = s00*A00 + s01*A10, m01 = s00*A01 + s01*A11;
                double m10 = s10*A00 + s11*A10, m11 = s10*A01 + s11*A11;
                for (int s = 0; s < 7; s++) {
                    Pw[s][0] = (float)m00; Pw[s][1] = (float)m01;
                    Pw[s][2] = (float)m10; Pw[s][3] = (float)m11;
                    double n00 = m00*m00 + m01*m10, n01 = m00*m01 + m01*m11;
                    double n10 = m10*m00 + m11*m10, n11 = m10*m01 + m11*m11;
                    m00 = n00; m01 = n01; m10 = n10; m11 = n11;
                }
            }
            __syncthreads();

            for (int s = 0; s < 7; s++) {
                int off = 1 << s;
                float ax = 0.f, ay = 0.f;
                if (t < 128 && t >= off) {
                    float2 src = sv[t - off];
                    ax = Pw[s][0] * src.x + Pw[s][1] * src.y;
                    ay = Pw[s][2] * src.x + Pw[s][3] * src.y;
                }
                __syncthreads();
                if (t < 128) { sv[t].x += ax; sv[t].y += ay; }
                __syncthreads();
            }

            if (t < 128) {
                float py1 = 0.f, py2 = 0.f;
                if (t > 0) { py1 = sv[t - 1].x; py2 = sv[t - 1].y; }
                #pragma unroll
                for (int i = 0; i < 7; i++) {
                    float cn = b0 * in[base + i] + b1 * in[base + i - 1] + b2 * in[base + i - 2];
                    float yn = cn - a1 * py1 - a2 * py2;
                    py2 = py1; py1 = yn;
                    if (f == 0) ys[base + i] = yn;
                    else { int g = 7 * t + i; if (g < W) g_wt[g] = yn; }
                }
            }
            __syncthreads();
        }
    }
}

// ============================================================
// Kernel B <<<84,256>>>: comb_A (blocks 0..7) + gbar + Bdirect
// ============================================================
__global__ void __launch_bounds__(256) ks_comb() {
    __shared__ union {
        struct { float f[FSZ]; float Ks[256]; } a;
        struct { float f[FB];  float Ks[512]; } b;
    } smc;
    int blk = blockIdx.x, t = threadIdx.x;

    // ---------------- phase 1: comb_A on blocks 0..7
    if (blk < NG) {
        float* f  = smc.a.f;
        float* Ks = smc.a.Ks;
        int g = blk;
        for (int p = t; p < g_Kwk[1]; p += 256) Ks[p] = g_Kt[p];
        int wk = g_Kwk[1], off = g_Koff[1];
        int c1 = g * GLEN;
        int len = (g == NG - 1) ? (NCH - (NG - 1) * GLEN) : GLEN;
        int cend  = c1 + len;
        int cendT = (g == NG - 1) ? (NCH - 1) : cend;

        int cbeg;
        if (g == 0) {
            for (int p = t; p < W; p += 256) {
                float v = g_wt[p];
                f_write(f, p, v);
                g_vstart[p] = v;
            }
            cbeg = 1;
        } else {
            for (int p = t; p < W; p += 256) {
                float v = g_dstate[c1 * WP + p];
                f_write(f, p, v);
                g_vstart[(c1 + 1) * WP + p] = v;
            }
            cbeg = c1 + 2;
        }
        __syncthreads();

        int o0 = t * 4;
        bool activ = o0 < W;
        float4 dv = make_float4(0.f, 0.f, 0.f, 0.f);
        if (activ) dv = *(const float4*)(g_dstate + (size_t)(cbeg - 1) * WP + o0);

        for (int c = cbeg; c <= cendT; c++) {
            float4 dnext = make_float4(0.f, 0.f, 0.f, 0.f);
            if (activ && c <= cendT - 1)
                dnext = *(const float4*)(g_dstate + (size_t)c * WP + o0);

            float acc[4] = {dv.x, dv.y, dv.z, dv.w};
            if (activ) conv_into(f, Ks, wk, off, o0, acc);
            __syncthreads();
            if (activ) {
                float* dst;
                if (c < cend) dst = g_vstart + (size_t)c * WP + o0;
                else dst = g_sA + (size_t)(g + 1) * WP + o0;   // X_1 (g=0) / Z_g
                #pragma unroll
                for (int e = 0; e < 4; e++) {
                    int p = o0 + e;
                    if (p < W) { f_write(f, p, acc[e]); dst[e] = acc[e]; }
                }
            }
            __syncthreads();
            dv = dnext;
        }
    }
    gbar(NCV * 4);

    // ---------------- phase 2: Bdirect on all 84 blocks
    {
        float* f  = smc.b.f;
        float* Ks = smc.b.Ks;
        int cid = blk >> 2, q = blk & 3;

        int g = 2;
        #pragma unroll
        for (int gg = 3; gg <= 7; gg++)
            if (cid >= (gg - 2) * (gg - 1) / 2) g = gg;
        int m = cid - (g - 2) * (g - 1) / 2;
        int srcRow = g - m - 1;

        int wk = g_KBwk[m], c0a = g_KBc0[m];
        for (int p = t; p < wk; p += 256) Ks[p] = g_KtB[m * 512 + p];

        for (int p = t; p < W; p += 256) {
            float v = __ldcg(g_sA + (size_t)srcRow * WP + p);
            #pragma unroll
            for (int n = 0; n < 6; n++) {
                int tt = p + n * W;
                if (tt < FB) f[tt] = v;
            }
        }
        __syncthreads();

        int o = q * QOUT + t;
        if (t < QOUT && o < W) {
            float acc = 0.f;
            int base = o - c0a - wk + 1 + LIFT;
            #pragma unroll 4
            for (int jj = 0; jj < wk; jj += 4) {
                float4 k4 = *(const float4*)&Ks[jj];
                acc = fmaf(k4.x, f[base + jj],     acc);
                acc = fmaf(k4.y, f[base + jj + 1], acc);
                acc = fmaf(k4.z, f[base + jj + 2], acc);
                acc = fmaf(k4.w, f[base + jj + 3], acc);
            }
            g_cv[(size_t)cid * WP + o] = acc;
        }
    }
}

// ============================================================
// Kernel C <<<149,896>>>: pass2 with comb_C correction prologue
// ============================================================
__global__ void __launch_bounds__(896) ksC(const float* __restrict__ uscr) {
    __shared__ SmemKS sm;
    __shared__ __align__(16) float f[FSZ];
    __shared__ __align__(16) float Ks[256];
    int c = blockIdx.x, i = threadIdx.x;
    bool act = i < W;
    int im1 = (i == 0) ? (W - 1) : (i - 1);
    int im2 = (i <= 1) ? (i + W - 2) : (i - 2);
    float d2 = g_par[0];

    float a;
    if (c < GLEN) {
        a = act ? g_vstart[(size_t)c * WP + i] : 0.0f;
        __syncthreads();
    } else {
        int g = c / GLEN, r = c - g * GLEN;
        for (int p = i; p < W; p += 896) f_write(f, p, xval(g, p));
        int wk = 0, off = 0;
        if (r > 0) {
            wk = g_Kwk[r]; off = g_Koff[r];
            if (i < wk) Ks[i] = g_Kt[(r - 1) * 256 + i];
        }
        __syncthreads();
        if (r == 0) {
            a = act ? f[i + AOFF] : 0.0f;        // X_g directly
        } else {
            int o0 = i * 4;
            if (o0 < W) {
                const float* vp = g_vstart + (size_t)c * WP + o0;
                float acc[4] = {vp[0], vp[1], vp[2], vp[3]};
                conv_into(f, Ks, wk, off, o0, acc);
                #pragma unroll
                for (int e = 0; e < 4; e++)
                    if (o0 + e < W) sm.ush[0][o0 + e] = acc[e];
            }
            __syncthreads();
            a = act ? sm.ush[0][i] : 0.0f;
            __syncthreads();
        }
    }

    const float* up = uscr + (size_t)c * MCH * W + i;
    float*       op = g_ks + (size_t)c * MCH * W + i;

    if (c < NCH - 1) {
        ks_run2<MCH / 2, false>(up, nullptr, op, a, sm.bsh, sm.ush, act, i, im1, im2, d2, 0.f);
    } else {
        ks_run2<LASTS / 2, false>(up, nullptr, op, a, sm.bsh, sm.ush, act, i, im1, im2, d2, 0.f);
        __syncthreads();
        if (act) sm.bsh[0][i] = a;
        __syncthreads();
        if (i < REM) {
            float fin = d2 * (sm.bsh[0][i] + sm.bsh[0][im1]);
            int g = NB * W + i;
            if (g >= N_TOT - 256) fin *= (float)(N_TOT - 1 - g) * (1.0f / 255.0f);
            g_ks[g] = fin;
        }
    }
}

// ============================================================
// Band-reject slab machinery (R12 recurrence, measured good)
// ============================================================
__device__ __forceinline__ void bq_load_slab(float* sl, int sb, int w, int l) {
    const float4* gp = (const float4*)(g_ks + (size_t)sb * SPB + (size_t)w * 2048);
    #pragma unroll
    for (int i = 0; i < 16; i++) {
        float4 v = gp[i * 32 + l];
        int s4 = i * 128 + l * 4;
        int c = s4 >> 6, k = s4 & 63;
        float* q = sl + c * 65 + k;
        q[0] = v.x; q[1] = v.y; q[2] = v.z; q[3] = v.w;
    }
}

__device__ __forceinline__ float2 bq_zero_scan(const float* slab, int sb, int t,
                                               int w, int l,
                                               float b0, float b1, float b2,
                                               float a1, float a2,
                                               float& hx1, float& hx2) {
    if (t == 0) {
        size_t s0 = (size_t)sb * SPB;
        hx1 = sb ? g_ks[s0 - 1] : 0.f;
        hx2 = sb ? g_ks[s0 - 2] : 0.f;
    } else {
        int pw = (t - 1) >> 5, pl = (t - 1) & 31;
        const float* pv = slab + pw * SLAB + pl * 65;
        hx1 = pv[63]; hx2 = pv[62];
    }
    const float* cp = slab + w * SLAB + l * 65;
    float x1 = hx1, x2 = hx2, y1 = 0.f, y2 = 0.f;
    #pragma unroll
    for (int k = 0; k < 64; k++) {
        float xn = cp[k];
        float yn = fmaf(b0, xn, fmaf(b1, x1, b2 * x2)) - fmaf(a1, y1, a2 * y2);
        x2 = x1; x1 = xn; y2 = y1; y1 = yn;
    }
    float2 v = make_float2(y1, y2);
    #pragma unroll
    for (int s = 0; s < 5; s++) {
        int off = 1 << s;
        float px = __shfl_up_sync(0xffffffffu, v.x, off);
        float py = __shfl_up_sync(0xffffffffu, v.y, off);
        if (l >= off) {
            float A, B, C, D; mload(s, A, B, C, D);
            v.x = fmaf(A, px, fmaf(B, py, v.x));
            v.y = fmaf(C, px, fmaf(D, py, v.y));
        }
    }
    return v;
}

__global__ void __launch_bounds__(BQTH) bq_passA() {
    __shared__ __align__(16) float slab[BQW * SLAB];
    __shared__ float2 wag[BQW];
    int sb = blockIdx.x, t = threadIdx.x, w = t >> 5, l = t & 31;
    float b0 = g_par[2], b1 = g_par[3], b2 = g_par[4], a1 = g_par[5], a2 = g_par[6];

    bq_load_slab(slab + w * SLAB, sb, w, l);
    __syncthreads();

    float hx1, hx2;
    float2 v = bq_zero_scan(slab, sb, t, w, l, b0, b1, b2, a1, a2, hx1, hx2);
    if (l == 31) wag[w] = v;
    __syncthreads();

    if (t == BQTH - 1) {
        float A, B, C, D; mload(5, A, B, C, D);   // M^2048
        float2 P = wag[0];
        #pragma unroll
        for (int u = 1; u < BQW; u++) {
            float2 nw = wag[u];
            P = make_float2(nw.x + A * P.x + B * P.y, nw.y + C * P.x + D * P.y);
        }
        g_blk[sb] = P;
    }
}

// ============================================================
// bq_passB: redundant per-block exclusive scan of slab
// aggregates (replaces bq_scanK), then exact replay + envelope.
// ============================================================
__global__ void __launch_bounds__(BQTH) bq_passB(float* __restrict__ out) {
    __shared__ __align__(16) float slab[BQW * SLAB];
    __shared__ float2 wag[BQW];
    __shared__ float2 tag[BQTH];
    __shared__ float2 bpsh;
    int sb = blockIdx.x, t = threadIdx.x, w = t >> 5, l = t & 31;
    float b0 = g_par[2], b1 = g_par[3], b2 = g_par[4], a1 = g_par[5], a2 = g_par[6];

    // ---- redundant exclusive prefix of 1024 slab aggregates (for this sb)
    float2 loc[8];
    {
        float A, B, C, D; mload(7, A, B, C, D);            // M^8192
        float2 Pacc = make_float2(0.f, 0.f);
        const float4* gb = (const float4*)g_blk;
        #pragma unroll
        for (int e = 0; e < 8; e += 2) {
            float4 q2 = gb[t * 4 + (e >> 1)];
            loc[e]     = make_float2(q2.x, q2.y);
            loc[e + 1] = make_float2(q2.z, q2.w);
            Pacc = make_float2(loc[e].x + A * Pacc.x + B * Pacc.y,
                               loc[e].y + C * Pacc.x + D * Pacc.y);
            Pacc = make_float2(loc[e + 1].x + A * Pacc.x + B * Pacc.y,
                               loc[e + 1].y + C * Pacc.x + D * Pacc.y);
        }
        tag[t] = Pacc;
    }
    __syncthreads();
    for (int s = 0; s < 7; s++) {
        int off = 1 << s;
        float E0, E1, E2, E3; mload(10 + s, E0, E1, E2, E3);   // M^(65536*2^s)
        float ax = 0.f, ay = 0.f;
        if (t >= off) {
            float2 src = tag[t - off];
            ax = fmaf(E0, src.x, E1 * src.y);
            ay = fmaf(E2, src.x, E3 * src.y);
        }
        __syncthreads();
        tag[t].x += ax; tag[t].y += ay;
        __syncthreads();
    }
    if (t == (sb >> 3)) {
        float A, B, C, D; mload(7, A, B, C, D);
        float2 cur = t ? tag[t - 1] : make_float2(0.f, 0.f);
        int r = sb & 7;
        for (int e = 0; e < r; e++)
            cur = make_float2(loc[e].x + A * cur.x + B * cur.y,
                              loc[e].y + C * cur.x + D * cur.y);
        bpsh = cur;
    }

    // ---- slab load + zero-scan
    bq_load_slab(slab + w * SLAB, sb, w, l);
    __syncthreads();

    float hx1, hx2;
    float2 v = bq_zero_scan(slab, sb, t, w, l, b0, b1, b2, a1, a2, hx1, hx2);
    if (l == 31) wag[w] = v;
    __syncthreads();

    float2 P = make_float2(0.f, 0.f);
    {
        float A, B, C, D; mload(5, A, B, C, D);
        for (int u = 0; u < w; u++) {
            float2 nw = wag[u];
            P = make_float2(nw.x + A * P.x + B * P.y, nw.y + C * P.x + D * P.y);
        }
    }
    float ex = __shfl_up_sync(0xffffffffu, v.x, 1);
    float ey = __shfl_up_sync(0xffffffffu, v.y, 1);
    if (l == 0) { ex = 0.f; ey = 0.f; }
    {
        float ra, rb, rc, rd; mpow64(l, ra, rb, rc, rd);
        ex += ra * P.x + rb * P.y;
        ey += rc * P.x + rd * P.y;
    }
    {
        float2 Pb = bpsh;
        float ra, rb, rc, rd; mpow64(t, ra, rb, rc, rd);
        ex += ra * Pb.x + rb * Pb.y;
        ey += rc * Pb.x + rd * Pb.y;
    }

    // replay in-place with envelope
    {
        float ia = g_par[7], ir = g_par[8], sg = g_par[9];
        float* cp = slab + w * SLAB + l * 65;
        float x1 = hx1, x2 = hx2, y1 = ex, y2 = ey;
        size_t s0 = (size_t)sb * SPB + (size_t)t * 64;
        #pragma unroll
        for (int k = 0; k < 64; k++) {
            float xn = cp[k];
            float yn = fmaf(b0, xn, fmaf(b1, x1, b2 * x2)) - fmaf(a1, y1, a2 * y2);
            x2 = x1; x1 = xn; y2 = y1; y1 = yn;
            float fn = (float)(s0 + k);
            float e1 = fminf(fn * ia, 1.0f);
            float e2 = fminf(((float)(N_TOT - 1) - fn) * ir, 1.0f);
            cp[k] = yn * e1 * e2 * sg;
        }
    }
    __syncwarp();

    {
        const float* sl = slab + w * SLAB;
        float4* op = (float4*)(out + (size_t)sb * SPB + (size_t)w * 2048);
        #pragma unroll
        for (int i = 0; i < 16; i++) {
            int s4 = i * 128 + l * 4;
            int c = s4 >> 6, k = s4 & 63;
            const float* q = sl + c * 65 + k;
            op[i * 32 + l] = make_float4(q[0], q[1], q[2], q[3]);
        }
    }
}

// ============================================================
extern "C" void kernel_launch(void* const* d_in, const int* in_sizes, int n_in,
                              void* d_out, int out_size) {
    const float* fb  = (const float*)d_in[0];
    const float* wt  = (const float*)d_in[1];
    const float* h   = (const float*)d_in[2];
    const float* ep  = (const float*)d_in[3];
    const float* lp2 = (const float*)d_in[4];
    float* out = (float*)d_out;

    ksA<<<PREPB + NCH, 896>>>(fb, out, wt, h, ep, lp2);  // prep + pass1 (u -> out)
    ks_comb<<<NCV * 4, 256>>>();                          // comb_A + gbar + Bdirect
    ksC<<<NCH, 896>>>(out);                               // comb_C prologue + pass2
    bq_passA<<<NBQB, BQTH>>>();
    bq_passB<<<NBQB, BQTH>>>(out);                        // fused scanK + replay
}

// round 16
// speedup vs baseline: 1.4223x; 1.0174x over previous
#include <cuda_runtime.h>
#include <math.h>

#ifndef M_PI
#define M_PI 3.14159265358979323846
#endif

#define N_TOT   8388608
#define W       882
#define WP      884
#define NB      9510
#define REM     788
#define MCH     64
#define NCH     149
#define LASTS   38
#define GLEN    19
#define NG      8
#define AOFF    860
#define FSZ     1756
#define SRATE   44100.0

// band-reject slab geometry: LBQ=32 (halved serial chain)
#define LBQ     32
#define BQW     4
#define BQTH    128
#define SLAB    1056          // 32 chunks * 33 floats per warp slab
#define SPB     4096          // samples per slab (128 chunks * 32)
#define NBQB    2048          // slabs

// comb_Bdirect geometry
#define QOUT    224
#define NCV     21
#define FB      4800          // 6-copy periodic extension
#define LIFT    4410          // 5*W

#define PREPB   46            // prep blocks at front of kernel A

// ---- scratch ----
__device__ float  g_wt[W];
__device__ float  g_dstate[NCH * WP];
__device__ float  g_vstart[NCH * WP];
__device__ float  g_sA[NG * WP];         // row1 = X_1, rows 2..7 = Z_1..Z_6
__device__ float  g_cv[NCV * WP];        // conv partials
__device__ float  g_ks[N_TOT];
__device__ float2 g_blk[NBQB];
__device__ float  g_MsF[18][4];          // M^(32 * 2^s), s=0..17
__device__ float  g_par[12];             // 0:d2 1:fa2 2..6:bq 7:ia 8:ir 9:sg
__device__ float  g_Kt[GLEN * 256];      // reversed folded taps S^(64k), k=1..19
__device__ float  g_KtB[6 * 512];        // reversed UNfolded taps S^(64*19m), m=1..6
__device__ int    g_Kwk[GLEN + 1], g_Koff[GLEN + 1];
__device__ int    g_KBwk[6], g_KBc0[6];
__device__ unsigned g_bar;

// ---- grid barrier (comb kernel only; 84 blocks) ----
__device__ __forceinline__ void gbar(unsigned target) {
    __threadfence();
    __syncthreads();
    if (threadIdx.x == 0) {
        atomicAdd(&g_bar, 1u);
        while (*(volatile unsigned*)&g_bar < target) { }
    }
    __syncthreads();
    __threadfence();
}

// kernel geometry for S^(64k), window folded mod W
__device__ __forceinline__ void kgeom2(int k, int& c0e, int& wk, int& jb) {
    int m = 64 * k;
    int hw = (int)ceil(21.0 * sqrt((double)k));
    int c0 = m / 2 - hw;
    wk = (2 * hw + 4) & ~3;
    int red = (c0 / W) * W;
    int ce = c0 - red;
    ce -= (ce + wk - 1) & 3;      // force (ce+wk) % 4 == 1
    c0e = ce;
    jb = ce + red;
}

// unfolded geometry for comb_Bdirect kernels, k = 19*(m+1)
__device__ __forceinline__ void kgeomB(int k, int& c0a, int& wk) {
    int m = 64 * k;
    int hw = (int)ceil(21.0 * sqrt((double)k));
    c0a = m / 2 - hw;
    wk = (2 * hw + 4) & ~3;
}

__device__ __forceinline__ float ftanh2(float x2) {   // x2 = 2*x
    float e = __expf(x2);
    return __fdividef(e - 1.0f, e + 1.0f);
}

__device__ __forceinline__ void mload(int s, float& A, float& B, float& C, float& D) {
    A = g_MsF[s][0]; B = g_MsF[s][1]; C = g_MsF[s][2]; D = g_MsF[s][3];
}
// M^(32*e) via binary composition over the rebased table
__device__ __forceinline__ void mpow32(int e, float& ra, float& rb, float& rc, float& rd) {
    ra = 1.f; rb = 0.f; rc = 0.f; rd = 1.f;
    for (int s = 0; e; s++, e >>= 1) {
        if (e & 1) {
            float A, B, C, D; mload(s, A, B, C, D);
            float na = A * ra + B * rc, nb = A * rb + B * rd;
            float nc = C * ra + D * rc, nd = C * rb + D * rd;
            ra = na; rb = nb; rc = nc; rd = nd;
        }
    }
}

// f[] circular extension: f[t] = v[(t - AOFF) mod W]
__device__ __forceinline__ void f_write(float* f, int p, float v) {
    f[p + AOFF] = v;
    if (p >= W - AOFF) f[p - (W - AOFF)] = v;
    if (p < FSZ - (W + AOFF)) f[p + W + AOFF] = v;
}

__device__ __forceinline__ void conv_into(const float* __restrict__ f,
                                          const float* __restrict__ Ks,
                                          int wk, int off, int o0, float* acc) {
    int b0 = o0 + off;
    float4 da = *(const float4*)&f[b0];
    #pragma unroll 2
    for (int jj = 0; jj < wk; jj += 4) {
        float4 ka = *(const float4*)&Ks[jj];
        float4 db = *(const float4*)&f[b0 + jj + 4];
        acc[0] = fmaf(ka.x, da.x, acc[0]); acc[0] = fmaf(ka.y, da.y, acc[0]);
        acc[0] = fmaf(ka.z, da.z, acc[0]); acc[0] = fmaf(ka.w, da.w, acc[0]);
        acc[1] = fmaf(ka.x, da.y, acc[1]); acc[1] = fmaf(ka.y, da.z, acc[1]);
        acc[1] = fmaf(ka.z, da.w, acc[1]); acc[1] = fmaf(ka.w, db.x, acc[1]);
        acc[2] = fmaf(ka.x, da.z, acc[2]); acc[2] = fmaf(ka.y, da.w, acc[2]);
        acc[2] = fmaf(ka.z, db.x, acc[2]); acc[2] = fmaf(ka.w, db.y, acc[2]);
        acc[3] = fmaf(ka.x, da.w, acc[3]); acc[3] = fmaf(ka.y, db.x, acc[3]);
        acc[3] = fmaf(ka.z, db.y, acc[3]); acc[3] = fmaf(ka.w, db.z, acc[3]);
        da = db;
    }
}

// X_g assembled from Z_{g-1} + conv partials (fixed order = deterministic)
__device__ __forceinline__ float xval(int g, int p) {
    if (g == 1) return g_sA[WP + p];
    float v = g_sA[(size_t)g * WP + p];              // Z_{g-1}
    int base = (g - 2) * (g - 1) / 2;
    #pragma unroll 6
    for (int m = 0; m < 6; m++)
        if (m < g - 1) v += g_cv[(size_t)(base + m) * WP + p];
    return v;
}

// ============================================================
// Karplus runner: 2 steps per barrier round.
// ============================================================
template<int NR, bool P1>
__device__ __forceinline__ void ks_run2(const float* __restrict__ xin,
                                        float* __restrict__ uout,
                                        float* __restrict__ op,
                                        float& a,
                                        float (*bsh)[W], float (*ush)[W],
                                        bool act, int i, int im1, int im2,
                                        float d2, float fa2) {
    float xa[2], xb[2];
    #pragma unroll
    for (int q = 0; q < 2; q++) {
        xa[q] = act ? xin[(size_t)(2 * q) * W] : 0.f;
        xb[q] = act ? xin[(size_t)(2 * q + 1) * W] : 0.f;
    }
    #pragma unroll 2
    for (int r = 0; r < NR; r++) {
        float x0 = xa[r & 1], x1 = xb[r & 1];
        if (act && r + 2 < NR) {
            xa[r & 1] = xin[(size_t)(2 * r + 4) * W];
            xb[r & 1] = xin[(size_t)(2 * r + 5) * W];
        }
        float u0, u1;
        if (P1) {
            u0 = ftanh2(fa2 * x0);
            u1 = ftanh2(fa2 * x1);
            if (act) {
                uout[(size_t)(2 * r) * W] = u0;
                uout[(size_t)(2 * r + 1) * W] = u1;
            }
        } else { u0 = x0; u1 = x1; }

        float bb = a + u0;
        if (act) { bsh[r & 1][i] = bb; ush[r & 1][i] = u1; }
        __syncthreads();
        if (act) {
            float bm1 = bsh[r & 1][im1], bm2 = bsh[r & 1][im2];
            float u1m1 = ush[r & 1][im1];
            float a1  = d2 * (bb + bm1);
            float a1m = d2 * (bm1 + bm2);
            float a2  = d2 * ((a1 + u1) + (a1m + u1m1));
            if (!P1) {
                op[(size_t)(2 * r) * W] = a1;
                op[(size_t)(2 * r + 1) * W] = a2;
            }
            a = a2;
        }
    }
}

// ============================================================
// Kernel A <<<195,896>>>: prep (blocks 0..45) + pass1 (46..194)
// ============================================================
struct SmemKS { float bsh[2][W]; float ush[2][W]; };
struct SmemWT { float xs[898]; float ys[898]; float2 sv[128]; float Pw[7][4]; float cf[10]; };

__global__ void __launch_bounds__(896) ksA(const float* __restrict__ fb,
                                           float* __restrict__ uscr,
                                           const float* __restrict__ wavetable,
                                           const float* __restrict__ h,
                                           const float* __restrict__ envp,
                                           const float* __restrict__ lp2) {
    __shared__ union { SmemKS ks; SmemWT wt; } sm;
    int b = blockIdx.x, t = threadIdx.x;

    if (b >= PREPB) {
        // ---------------- pass1: zero-init chunk + tanh precompute
        int c = b - PREPB;
        int i = t;
        bool act = i < W;
        int im1 = (i == 0) ? (W - 1) : (i - 1);
        int im2 = (i <= 1) ? (i + W - 2) : (i - 2);
        float dec = fminf(fmaxf(h[0] * 0.1f + 0.9f, 0.9f), 0.999f);
        float d2 = dec * 0.5f;
        float fa2 = 2.0f * h[3];

        float a = 0.0f;
        const float* fp = fb   + (size_t)c * MCH * W + i;
        float*       up = uscr + (size_t)c * MCH * W + i;
        if (c < NCH - 1) {
            ks_run2<MCH / 2, true>(fp, up, nullptr, a, sm.ks.bsh, sm.ks.ush,
                                   act, i, im1, im2, d2, fa2);
            if (act) g_dstate[c * WP + i] = a;
        } else {
            ks_run2<LASTS / 2, true>(fp, up, nullptr, a, sm.ks.bsh, sm.ks.ush,
                                     act, i, im1, im2, d2, fa2);
        }
        return;
    }

    if (b >= 40) {
        // KB table rows (6 x 512 unfolded taps), t<128 active
        if (t < 128) {
            int idx = (b - 40) * 128 + t;
            double decay = (double)h[0] / 10.0 + 0.9;
            decay = fmin(fmax(decay, 0.9), 0.999);
            double ld2 = log(decay * 0.5);
            int m = idx / 512;
            int jj = idx % 512;
            int k = 19 * (m + 1);
            int c0a, wk; kgeomB(k, c0a, wk);
            int m64 = 64 * k;
            float val = 0.0f;
            if (jj < wk) {
                int j = c0a + wk - 1 - jj;
                if (j >= 0 && j <= m64) {
                    double lg = lgamma((double)(m64 + 1)) - lgamma((double)(j + 1))
                              - lgamma((double)(m64 - j + 1)) + (double)m64 * ld2;
                    val = (float)exp(lg);
                }
            }
            g_KtB[idx] = val;
        }
        return;
    }

    if (b >= 2) {
        // K table rows k=1..19, t<128 active
        if (t < 128) {
            int idx = (b - 2) * 128 + t;        // 38*128 = 4864
            double decay = (double)h[0] / 10.0 + 0.9;
            decay = fmin(fmax(decay, 0.9), 0.999);
            double ld2 = log(decay * 0.5);
            int k = idx / 256 + 1;
            int jj = idx % 256;
            int c0e, wk, jb; kgeom2(k, c0e, wk, jb);
            int m = 64 * k;
            float val = 0.0f;
            if (jj < wk) {
                int j = jb + wk - 1 - jj;
                if (j >= 0 && j <= m) {
                    double lg = lgamma((double)(m + 1)) - lgamma((double)(j + 1))
                              - lgamma((double)(m - j + 1)) + (double)m * ld2;
                    val = (float)exp(lg);
                }
            }
            g_Kt[idx] = val;
        }
        return;
    }

    if (b == 0) {
        // ---- scalars ----
        if (t >= 1 && t <= GLEN) {
            int c0e, wk, jb; kgeom2(t, c0e, wk, jb);
            g_Kwk[t] = wk;
            g_Koff[t] = AOFF + 1 - c0e - wk;
        }
        if (t >= 22 && t < 28) {
            int m = t - 22;
            int c0a, wk; kgeomB(19 * (m + 1), c0a, wk);
            g_KBwk[m] = wk;
            g_KBc0[m] = c0a;
        }
        if (t != 0) return;

        g_bar = 0;

        double decay = (double)h[0] / 10.0 + 0.9;
        decay = fmin(fmax(decay, 0.9), 0.999);

        double h5 = h[5], h6 = h[6];
        double brf = h5 * SRATE / 4.0; brf = fmin(fmax(brf, 100.0), SRATE / 2.0 - 1.0);
        double brq = fmin(fmax(h6, 0.1), 0.999);
        double w0b = 2.0 * M_PI * brf / SRATE, alb = sin(w0b) / (2.0 * brq), cwb = cos(w0b);
        double a0b = 1.0 + alb;
        double bb0 = 1.0 / a0b, bb1 = (-2.0 * cwb) / a0b;
        double ba1 = (-2.0 * cwb) / a0b, ba2 = (1.0 - alb) / a0b;

        {
            double m00 = -ba1, m01 = -ba2, m10 = 1.0, m11 = 0.0;
            for (int s = 0; s < 5; s++) {                    // -> M^32
                double n00 = m00 * m00 + m01 * m10, n01 = m00 * m01 + m01 * m11;
                double n10 = m10 * m00 + m11 * m10, n11 = m10 * m01 + m11 * m11;
                m00 = n00; m01 = n01; m10 = n10; m11 = n11;
            }
            for (int s = 0; s < 18; s++) {                   // M^(32*2^s)
                g_MsF[s][0] = (float)m00; g_MsF[s][1] = (float)m01;
                g_MsF[s][2] = (float)m10; g_MsF[s][3] = (float)m11;
                double n00 = m00 * m00 + m01 * m10, n01 = m00 * m01 + m01 * m11;
                double n10 = m10 * m00 + m11 * m10, n11 = m10 * m01 + m11 * m11;
                m00 = n00; m01 = n01; m10 = n10; m11 = n11;
            }
        }

        double nD = (double)N_TOT;
        double attack  = 1.0 + (double)envp[0] * 0.1 * nD;
        double release = 1.0 + (double)envp[2] * 0.1 * nD;
        double sustain = fmin(fmax((double)envp[1], 0.0), 1.0);

        g_par[0] = (float)(decay * 0.5);
        g_par[1] = (float)(2.0 * (double)h[3]);
        g_par[2] = (float)bb0; g_par[3] = (float)bb1; g_par[4] = (float)bb0;
        g_par[5] = (float)ba1; g_par[6] = (float)ba2;
        g_par[7] = (float)(1.0 / attack);
        g_par[8] = (float)(1.0 / release);
        g_par[9] = (float)(sustain * (double)h[4]);
        return;
    }

    // ---- b == 1: wavetable prefilter (t<128 active; barriers all-thread) ----
    {
        float* xs = sm.wt.xs; float* ys = sm.wt.ys;
        float2* sv = sm.wt.sv; float (*Pw)[4] = sm.wt.Pw; float* cf = sm.wt.cf;

        if (t < 128)
            for (int p = t; p < 896; p += 128) xs[2 + p] = (p < W) ? wavetable[p] : 0.0f;
        if (t < 2) { xs[t] = 0.0f; ys[t] = 0.0f; }

        if (t == 0) {
            double h1 = h[1], h2 = h[2];
            double lpf = h1 * SRATE / 4.0; lpf = fmin(fmax(lpf, 100.0), SRATE / 2.0 - 1.0);
            double lpq = fmin(fmax(h2, 0.1), 0.999);
            double w0 = 2.0 * M_PI * lpf / SRATE, al = sin(w0) / (2.0 * lpq), cw = cos(w0);
            double a0 = 1.0 + al;
            cf[0] = (float)(((1.0 - cw) * 0.5) / a0);
            cf[1] = (float)((1.0 - cw) / a0);
            cf[2] = cf[0];
            cf[3] = (float)((-2.0 * cw) / a0);
            cf[4] = (float)((1.0 - al) / a0);
            double c2 = 100.0 + (double)lp2[0] * 8000.0;
            double w02 = 2.0 * M_PI * c2 / SRATE, al2 = sin(w02) / (2.0 * 0.707), cw2 = cos(w02);
            double a02 = 1.0 + al2;
            cf[5] = (float)(((1.0 - cw2) * 0.5) / a02);
            cf[6] = (float)((1.0 - cw2) / a02);
            cf[7] = cf[5];
            cf[8] = (float)((-2.0 * cw2) / a02);
            cf[9] = (float)((1.0 - al2) / a02);
        }
        __syncthreads();

        #pragma unroll
        for (int f = 0; f < 2; f++) {
            float b0 = cf[5 * f + 0], b1 = cf[5 * f + 1], b2 = cf[5 * f + 2];
            float a1 = cf[5 * f + 3], a2 = cf[5 * f + 4];
            const float* in = (f == 0) ? xs : ys;
            int base = 2 + 7 * (t & 127);

            if (t < 128) {
                float y1 = 0.f, y2 = 0.f;
                #pragma unroll
                for (int i = 0; i < 7; i++) {
                    float cn = b0 * in[base + i] + b1 * in[base + i - 1] + b2 * in[base + i - 2];
                    float yn = cn - a1 * y1 - a2 * y2;
                    y2 = y1; y1 = yn;
                }
                sv[t] = make_float2(y1, y2);
            }
            if (t == 0) {
                double A00 = -(double)a1, A01 = -(double)a2, A10 = 1.0, A11 = 0.0;
                double q00 = A00*A00 + A01*A10, q01 = A00*A01 + A01*A11;
                double q10 = A10*A00 + A11*A10, q11 = A10*A01 + A11*A11;
                double r00 = q00*q00 + q01*q10, r01 = q00*q01 + q01*q11;
                double r10 = q10*q00 + q11*q10, r11 = q10*q01 + q11*q11;
                double s00 = r00*q00 + r01*q10, s01 = r00*q01 + r01*q11;
                double s10 = r10*q00 + r11*q10, s11 = r10*q01 + r11*q11;
                double m00 = s00*A00 + s01*A10, m01 = s00*A01 + s01*A11;
                double m10 = s10*A00 + s11*A10, m11 = s10*A01 + s11*A11;
                for (int s = 0; s < 7; s++) {
                    Pw[s][0] = (float)m00; Pw[s][1] = (float)m01;
                    Pw[s][2] = (float)m10; Pw[s][3] = (float)m11;
                    double n00 = m00*m00 + m01*m10, n01 = m00*m01 + m01*m11;
                    double n10 = m10*m00 + m11*m10, n11 = m10*m01 + m11*m11;
                    m00 = n00; m01 = n01; m10 = n10; m11 = n11;
                }
            }
            __syncthreads();

            for (int s = 0; s < 7; s++) {
                int off = 1 << s;
                float ax = 0.f, ay = 0.f;
                if (t < 128 && t >= off) {
                    float2 src = sv[t - off];
                    ax = Pw[s][0] * src.x + Pw[s][1] * src.y;
                    ay = Pw[s][2] * src.x + Pw[s][3] * src.y;
                }
                __syncthreads();
                if (t < 128) { sv[t].x += ax; sv[t].y += ay; }
                __syncthreads();
            }

            if (t < 128) {
                float py1 = 0.f, py2 = 0.f;
                if (t > 0) { py1 = sv[t - 1].x; py2 = sv[t - 1].y; }
                #pragma unroll
                for (int i = 0; i < 7; i++) {
                    float cn = b0 * in[base + i] + b1 * in[base + i - 1] + b2 * in[base + i - 2];
                    float yn = cn - a1 * py1 - a2 * py2;
                    py2 = py1; py1 = yn;
                    if (f == 0) ys[base + i] = yn;
                    else { int g = 7 * t + i; if (g < W) g_wt[g] = yn; }
                }
            }
            __syncthreads();
        }
    }
}

// ============================================================
// Kernel B <<<84,256>>>: comb_A (blocks 0..7) + gbar + Bdirect
// ============================================================
__global__ void __launch_bounds__(256) ks_comb() {
    __shared__ union {
        struct { float f[FSZ]; float Ks[256]; } a;
        struct { float f[FB];  float Ks[512]; } b;
    } smc;
    int blk = blockIdx.x, t = threadIdx.x;

    // ---------------- phase 1: comb_A on blocks 0..7
    if (blk < NG) {
        float* f  = smc.a.f;
        float* Ks = smc.a.Ks;
        int g = blk;
        for (int p = t; p < g_Kwk[1]; p += 256) Ks[p] = g_Kt[p];
        int wk = g_Kwk[1], off = g_Koff[1];
        int c1 = g * GLEN;
        int len = (g == NG - 1) ? (NCH - (NG - 1) * GLEN) : GLEN;
        int cend  = c1 + len;
        int cendT = (g == NG - 1) ? (NCH - 1) : cend;

        int cbeg;
        if (g == 0) {
            for (int p = t; p < W; p += 256) {
                float v = g_wt[p];
                f_write(f, p, v);
                g_vstart[p] = v;
            }
            cbeg = 1;
        } else {
            for (int p = t; p < W; p += 256) {
                float v = g_dstate[c1 * WP + p];
                f_write(f, p, v);
                g_vstart[(c1 + 1) * WP + p] = v;
            }
            cbeg = c1 + 2;
        }
        __syncthreads();

        int o0 = t * 4;
        bool activ = o0 < W;
        float4 dv = make_float4(0.f, 0.f, 0.f, 0.f);
        if (activ) dv = *(const float4*)(g_dstate + (size_t)(cbeg - 1) * WP + o0);

        for (int c = cbeg; c <= cendT; c++) {
            float4 dnext = make_float4(0.f, 0.f, 0.f, 0.f);
            if (activ && c <= cendT - 1)
                dnext = *(const float4*)(g_dstate + (size_t)c * WP + o0);

            float acc[4] = {dv.x, dv.y, dv.z, dv.w};
            if (activ) conv_into(f, Ks, wk, off, o0, acc);
            __syncthreads();
            if (activ) {
                float* dst;
                if (c < cend) dst = g_vstart + (size_t)c * WP + o0;
                else dst = g_sA + (size_t)(g + 1) * WP + o0;   // X_1 (g=0) / Z_g
                #pragma unroll
                for (int e = 0; e < 4; e++) {
                    int p = o0 + e;
                    if (p < W) { f_write(f, p, acc[e]); dst[e] = acc[e]; }
                }
            }
            __syncthreads();
            dv = dnext;
        }
    }
    gbar(NCV * 4);

    // ---------------- phase 2: Bdirect on all 84 blocks
    {
        float* f  = smc.b.f;
        float* Ks = smc.b.Ks;
        int cid = blk >> 2, q = blk & 3;

        int g = 2;
        #pragma unroll
        for (int gg = 3; gg <= 7; gg++)
            if (cid >= (gg - 2) * (gg - 1) / 2) g = gg;
        int m = cid - (g - 2) * (g - 1) / 2;
        int srcRow = g - m - 1;

        int wk = g_KBwk[m], c0a = g_KBc0[m];
        for (int p = t; p < wk; p += 256) Ks[p] = g_KtB[m * 512 + p];

        for (int p = t; p < W; p += 256) {
            float v = __ldcg(g_sA + (size_t)srcRow * WP + p);
            #pragma unroll
            for (int n = 0; n < 6; n++) {
                int tt = p + n * W;
                if (tt < FB) f[tt] = v;
            }
        }
        __syncthreads();

        int o = q * QOUT + t;
        if (t < QOUT && o < W) {
            float acc = 0.f;
            int base = o - c0a - wk + 1 + LIFT;
            #pragma unroll 4
            for (int jj = 0; jj < wk; jj += 4) {
                float4 k4 = *(const float4*)&Ks[jj];
                acc = fmaf(k4.x, f[base + jj],     acc);
                acc = fmaf(k4.y, f[base + jj + 1], acc);
                acc = fmaf(k4.z, f[base + jj + 2], acc);
                acc = fmaf(k4.w, f[base + jj + 3], acc);
            }
            g_cv[(size_t)cid * WP + o] = acc;
        }
    }
}

// ============================================================
// Kernel C <<<149,896>>>: pass2 with comb_C correction prologue
// ============================================================
__global__ void __launch_bounds__(896) ksC(const float* __restrict__ uscr) {
    __shared__ SmemKS sm;
    __shared__ __align__(16) float f[FSZ];
    __shared__ __align__(16) float Ks[256];
    int c = blockIdx.x, i = threadIdx.x;
    bool act = i < W;
    int im1 = (i == 0) ? (W - 1) : (i - 1);
    int im2 = (i <= 1) ? (i + W - 2) : (i - 2);
    float d2 = g_par[0];

    float a;
    if (c < GLEN) {
        a = act ? g_vstart[(size_t)c * WP + i] : 0.0f;
        __syncthreads();
    } else {
        int g = c / GLEN, r = c - g * GLEN;
        for (int p = i; p < W; p += 896) f_write(f, p, xval(g, p));
        int wk = 0, off = 0;
        if (r > 0) {
            wk = g_Kwk[r]; off = g_Koff[r];
            if (i < wk) Ks[i] = g_Kt[(r - 1) * 256 + i];
        }
        __syncthreads();
        if (r == 0) {
            a = act ? f[i + AOFF] : 0.0f;        // X_g directly
        } else {
            int o0 = i * 4;
            if (o0 < W) {
                const float* vp = g_vstart + (size_t)c * WP + o0;
                float acc[4] = {vp[0], vp[1], vp[2], vp[3]};
                conv_into(f, Ks, wk, off, o0, acc);
                #pragma unroll
                for (int e = 0; e < 4; e++)
                    if (o0 + e < W) sm.ush[0][o0 + e] = acc[e];
            }
            __syncthreads();
            a = act ? sm.ush[0][i] : 0.0f;
            __syncthreads();
        }
    }

    const float* up = uscr + (size_t)c * MCH * W + i;
    float*       op = g_ks + (size_t)c * MCH * W + i;

    if (c < NCH - 1) {
        ks_run2<MCH / 2, false>(up, nullptr, op, a, sm.bsh, sm.ush, act, i, im1, im2, d2, 0.f);
    } else {
        ks_run2<LASTS / 2, false>(up, nullptr, op, a, sm.bsh, sm.ush, act, i, im1, im2, d2, 0.f);
        __syncthreads();
        if (act) sm.bsh[0][i] = a;
        __syncthreads();
        if (i < REM) {
            float fin = d2 * (sm.bsh[0][i] + sm.bsh[0][im1]);
            int g = NB * W + i;
            if (g >= N_TOT - 256) fin *= (float)(N_TOT - 1 - g) * (1.0f / 255.0f);
            g_ks[g] = fin;
        }
    }
}

// ============================================================
// Band-reject slab machinery, LBQ=32 (stride-33 slab layout)
// ============================================================
__device__ __forceinline__ void bq_load_slab(float* sl, int sb, int w, int l) {
    const float4* gp = (const float4*)(g_ks + (size_t)sb * SPB + (size_t)w * 1024);
    #pragma unroll
    for (int i = 0; i < 8; i++) {
        float4 v = gp[i * 32 + l];
        int s4 = i * 128 + l * 4;
        int c = s4 >> 5, k = s4 & 31;
        float* q = sl + c * 33 + k;
        q[0] = v.x; q[1] = v.y; q[2] = v.z; q[3] = v.w;
    }
}

__device__ __forceinline__ float2 bq_zero_scan(const float* slab, int sb, int t,
                                               int w, int l,
                                               float b0, float b1, float b2,
                                               float a1, float a2,
                                               float& hx1, float& hx2) {
    if (t == 0) {
        size_t s0 = (size_t)sb * SPB;
        hx1 = sb ? g_ks[s0 - 1] : 0.f;
        hx2 = sb ? g_ks[s0 - 2] : 0.f;
    } else {
        int pw = (t - 1) >> 5, pl = (t - 1) & 31;
        const float* pv = slab + pw * SLAB + pl * 33;
        hx1 = pv[31]; hx2 = pv[30];
    }
    const float* cp = slab + w * SLAB + l * 33;
    float x1 = hx1, x2 = hx2, y1 = 0.f, y2 = 0.f;
    #pragma unroll
    for (int k = 0; k < 32; k++) {
        float xn = cp[k];
        float yn = fmaf(b0, xn, fmaf(b1, x1, b2 * x2)) - fmaf(a1, y1, a2 * y2);
        x2 = x1; x1 = xn; y2 = y1; y1 = yn;
    }
    float2 v = make_float2(y1, y2);
    #pragma unroll
    for (int s = 0; s < 5; s++) {
        int off = 1 << s;
        float px = __shfl_up_sync(0xffffffffu, v.x, off);
        float py = __shfl_up_sync(0xffffffffu, v.y, off);
        if (l >= off) {
            float A, B, C, D; mload(s, A, B, C, D);
            v.x = fmaf(A, px, fmaf(B, py, v.x));
            v.y = fmaf(C, px, fmaf(D, py, v.y));
        }
    }
    return v;
}

__global__ void __launch_bounds__(BQTH) bq_passA() {
    __shared__ __align__(16) float slab[BQW * SLAB];
    __shared__ float2 wag[BQW];
    int sb = blockIdx.x, t = threadIdx.x, w = t >> 5, l = t & 31;
    float b0 = g_par[2], b1 = g_par[3], b2 = g_par[4], a1 = g_par[5], a2 = g_par[6];

    bq_load_slab(slab + w * SLAB, sb, w, l);
    __syncthreads();

    float hx1, hx2;
    float2 v = bq_zero_scan(slab, sb, t, w, l, b0, b1, b2, a1, a2, hx1, hx2);
    if (l == 31) wag[w] = v;
    __syncthreads();

    if (t == BQTH - 1) {
        float A, B, C, D; mload(5, A, B, C, D);   // M^1024 (per-warp span)
        float2 P = wag[0];
        #pragma unroll
        for (int u = 1; u < BQW; u++) {
            float2 nw = wag[u];
            P = make_float2(nw.x + A * P.x + B * P.y, nw.y + C * P.x + D * P.y);
        }
        g_blk[sb] = P;
    }
}

// ============================================================
// bq_passB: redundant per-block exclusive scan of 2048 slab
// aggregates, then exact replay + envelope.
// ============================================================
__global__ void __launch_bounds__(BQTH) bq_passB(float* __restrict__ out) {
    __shared__ __align__(16) float slab[BQW * SLAB];
    __shared__ float2 wag[BQW];
    __shared__ float2 tag[BQTH];
    __shared__ float2 bpsh;
    int sb = blockIdx.x, t = threadIdx.x, w = t >> 5, l = t & 31;
    float b0 = g_par[2], b1 = g_par[3], b2 = g_par[4], a1 = g_par[5], a2 = g_par[6];

    // ---- redundant exclusive prefix of 2048 slab aggregates (for this sb)
    {
        float A, B, C, D; mload(7, A, B, C, D);            // M^4096 (slab span)
        float2 Pacc = make_float2(0.f, 0.f);
        const float4* gb = (const float4*)g_blk;
        #pragma unroll
        for (int j = 0; j < 8; j++) {                      // 16 aggregates streamed
            float4 q2 = gb[t * 8 + j];
            Pacc = make_float2(q2.x + A * Pacc.x + B * Pacc.y,
                               q2.y + C * Pacc.x + D * Pacc.y);
            Pacc = make_float2(q2.z + A * Pacc.x + B * Pacc.y,
                               q2.w + C * Pacc.x + D * Pacc.y);
        }
        tag[t] = Pacc;
    }
    __syncthreads();
    for (int s = 0; s < 7; s++) {
        int off = 1 << s;
        float E0, E1, E2, E3; mload(11 + s, E0, E1, E2, E3);   // M^(65536*2^s)
        float ax = 0.f, ay = 0.f;
        if (t >= off) {
            float2 src = tag[t - off];
            ax = fmaf(E0, src.x, E1 * src.y);
            ay = fmaf(E2, src.x, E3 * src.y);
        }
        __syncthreads();
        tag[t].x += ax; tag[t].y += ay;
        __syncthreads();
    }
    if (t == (sb >> 4)) {
        float A, B, C, D; mload(7, A, B, C, D);
        float2 cur = t ? tag[t - 1] : make_float2(0.f, 0.f);
        int r = sb & 15;
        for (int e = 0; e < r; e++) {
            float2 lv = g_blk[t * 16 + e];
            cur = make_float2(lv.x + A * cur.x + B * cur.y,
                              lv.y + C * cur.x + D * cur.y);
        }
        bpsh = cur;
    }

    // ---- slab load + zero-scan
    bq_load_slab(slab + w * SLAB, sb, w, l);
    __syncthreads();

    float hx1, hx2;
    float2 v = bq_zero_scan(slab, sb, t, w, l, b0, b1, b2, a1, a2, hx1, hx2);
    if (l == 31) wag[w] = v;
    __syncthreads();

    float2 P = make_float2(0.f, 0.f);
    {
        float A, B, C, D; mload(5, A, B, C, D);            // M^1024
        for (int u = 0; u < w; u++) {
            float2 nw = wag[u];
            P = make_float2(nw.x + A * P.x + B * P.y, nw.y + C * P.x + D * P.y);
        }
    }
    float ex = __shfl_up_sync(0xffffffffu, v.x, 1);
    float ey = __shfl_up_sync(0xffffffffu, v.y, 1);
    if (l == 0) { ex = 0.f; ey = 0.f; }
    {
        float ra, rb, rc, rd; mpow32(l, ra, rb, rc, rd);   // M^(32*l)
        ex += ra * P.x + rb * P.y;
        ey += rc * P.x + rd * P.y;
    }
    {
        float2 Pb = bpsh;
        float ra, rb, rc, rd; mpow32(t, ra, rb, rc, rd);   // M^(32*t)
        ex += ra * Pb.x + rb * Pb.y;
        ey += rc * Pb.x + rd * Pb.y;
    }

    // replay in-place with envelope
    {
        float ia = g_par[7], ir = g_par[8], sg = g_par[9];
        float* cp = slab + w * SLAB + l * 33;
        float x1 = hx1, x2 = hx2, y1 = ex, y2 = ey;
        size_t s0 = (size_t)sb * SPB + (size_t)t * 32;
        #pragma unroll
        for (int k = 0; k < 32; k++) {
            float xn = cp[k];
            float yn = fmaf(b0, xn, fmaf(b1, x1, b2 * x2)) - fmaf(a1, y1, a2 * y2);
            x2 = x1; x1 = xn; y2 = y1; y1 = yn;
            float fn = (float)(s0 + k);
            float e1 = fminf(fn * ia, 1.0f);
            float e2 = fminf(((float)(N_TOT - 1) - fn) * ir, 1.0f);
            cp[k] = yn * e1 * e2 * sg;
        }
    }
    __syncwarp();

    {
        const float* sl = slab + w * SLAB;
        float4* op = (float4*)(out + (size_t)sb * SPB + (size_t)w * 1024);
        #pragma unroll
        for (int i = 0; i < 8; i++) {
            int s4 = i * 128 + l * 4;
            int c = s4 >> 5, k = s4 & 31;
            const float* q = sl + c * 33 + k;
            op[i * 32 + l] = make_float4(q[0], q[1], q[2], q[3]);
        }
    }
}

// ============================================================
extern "C" void kernel_launch(void* const* d_in, const int* in_sizes, int n_in,
                              void* d_out, int out_size) {
    const float* fb  = (const float*)d_in[0];
    const float* wt  = (const float*)d_in[1];
    const float* h   = (const float*)d_in[2];
    const float* ep  = (const float*)d_in[3];
    const float* lp2 = (const float*)d_in[4];
    float* out = (float*)d_out;

    ksA<<<PREPB + NCH, 896>>>(fb, out, wt, h, ep, lp2);  // prep + pass1 (u -> out)
    ks_comb<<<NCV * 4, 256>>>();                          // comb_A + gbar + Bdirect
    ksC<<<NCH, 896>>>(out);                               // comb_C prologue + pass2
    bq_passA<<<NBQB, BQTH>>>();
    bq_passB<<<NBQB, BQTH>>>(out);                        // fused scan + replay
}

// round 17
// speedup vs baseline: 1.5698x; 1.1037x over previous
#include <cuda_runtime.h>
#include <math.h>

#ifndef M_PI
#define M_PI 3.14159265358979323846
#endif

#define N_TOT   8388608
#define W       882
#define WP      884
#define NB      9510
#define REM     788
#define MCH     64
#define NCH     149
#define LASTS   38
#define GLEN    19
#define NG      8
#define AOFF    860
#define FSZ     1756
#define SRATE   44100.0

// band-reject slab geometry (LBQ=32, measured good)
#define LBQ     32
#define BQW     4
#define BQTH    128
#define SLAB    1056
#define SPB     4096
#define NBQB    2048

// comb_Bdirect geometry
#define QOUT    224
#define NCV     21
#define FB      4800
#define LIFT    4410

#define PREPB   46

// ---- scratch ----
__device__ float  g_wt[W];
__device__ float  g_dstate[NCH * WP];
__device__ float  g_vstart[NCH * WP];
__device__ float  g_sA[NG * WP];
__device__ float  g_cv[NCV * WP];
__device__ float  g_ks[N_TOT];
__device__ float2 g_blk[NBQB];
__device__ float  g_MsF[18][4];          // M^(32 * 2^s), s=0..17
__device__ float  g_par[12];
__device__ float  g_Kt[GLEN * 256];
__device__ float  g_KtB[6 * 512];
__device__ int    g_Kwk[GLEN + 1], g_Koff[GLEN + 1];
__device__ int    g_KBwk[6], g_KBc0[6];
__device__ unsigned g_bar;

__device__ __forceinline__ void gbar(unsigned target) {
    __threadfence();
    __syncthreads();
    if (threadIdx.x == 0) {
        atomicAdd(&g_bar, 1u);
        while (*(volatile unsigned*)&g_bar < target) { }
    }
    __syncthreads();
    __threadfence();
}

__device__ __forceinline__ void kgeom2(int k, int& c0e, int& wk, int& jb) {
    int m = 64 * k;
    int hw = (int)ceil(21.0 * sqrt((double)k));
    int c0 = m / 2 - hw;
    wk = (2 * hw + 4) & ~3;
    int red = (c0 / W) * W;
    int ce = c0 - red;
    ce -= (ce + wk - 1) & 3;
    c0e = ce;
    jb = ce + red;
}

__device__ __forceinline__ void kgeomB(int k, int& c0a, int& wk) {
    int m = 64 * k;
    int hw = (int)ceil(21.0 * sqrt((double)k));
    c0a = m / 2 - hw;
    wk = (2 * hw + 4) & ~3;
}

__device__ __forceinline__ float ftanh2(float x2) {
    float e = __expf(x2);
    return __fdividef(e - 1.0f, e + 1.0f);
}

__device__ __forceinline__ void mload(int s, float& A, float& B, float& C, float& D) {
    A = g_MsF[s][0]; B = g_MsF[s][1]; C = g_MsF[s][2]; D = g_MsF[s][3];
}
__device__ __forceinline__ void mpow32(int e, float& ra, float& rb, float& rc, float& rd) {
    ra = 1.f; rb = 0.f; rc = 0.f; rd = 1.f;
    for (int s = 0; e; s++, e >>= 1) {
        if (e & 1) {
            float A, B, C, D; mload(s, A, B, C, D);
            float na = A * ra + B * rc, nb = A * rb + B * rd;
            float nc = C * ra + D * rc, nd = C * rb + D * rd;
            ra = na; rb = nb; rc = nc; rd = nd;
        }
    }
}

__device__ __forceinline__ void f_write(float* f, int p, float v) {
    f[p + AOFF] = v;
    if (p >= W - AOFF) f[p - (W - AOFF)] = v;
    if (p < FSZ - (W + AOFF)) f[p + W + AOFF] = v;
}

__device__ __forceinline__ void conv_into(const float* __restrict__ f,
                                          const float* __restrict__ Ks,
                                          int wk, int off, int o0, float* acc) {
    int b0 = o0 + off;
    float4 da = *(const float4*)&f[b0];
    #pragma unroll 2
    for (int jj = 0; jj < wk; jj += 4) {
        float4 ka = *(const float4*)&Ks[jj];
        float4 db = *(const float4*)&f[b0 + jj + 4];
        acc[0] = fmaf(ka.x, da.x, acc[0]); acc[0] = fmaf(ka.y, da.y, acc[0]);
        acc[0] = fmaf(ka.z, da.z, acc[0]); acc[0] = fmaf(ka.w, da.w, acc[0]);
        acc[1] = fmaf(ka.x, da.y, acc[1]); acc[1] = fmaf(ka.y, da.z, acc[1]);
        acc[1] = fmaf(ka.z, da.w, acc[1]); acc[1] = fmaf(ka.w, db.x, acc[1]);
        acc[2] = fmaf(ka.x, da.z, acc[2]); acc[2] = fmaf(ka.y, da.w, acc[2]);
        acc[2] = fmaf(ka.z, db.x, acc[2]); acc[2] = fmaf(ka.w, db.y, acc[2]);
        acc[3] = fmaf(ka.x, da.w, acc[3]); acc[3] = fmaf(ka.y, db.x, acc[3]);
        acc[3] = fmaf(ka.z, db.y, acc[3]); acc[3] = fmaf(ka.w, db.z, acc[3]);
        da = db;
    }
}

__device__ __forceinline__ float xval(int g, int p) {
    if (g == 1) return g_sA[WP + p];
    float v = g_sA[(size_t)g * WP + p];
    int base = (g - 2) * (g - 1) / 2;
    #pragma unroll 6
    for (int m = 0; m < 6; m++)
        if (m < g - 1) v += g_cv[(size_t)(base + m) * WP + p];
    return v;
}

// ============================================================
// Karplus runner: 2 steps per barrier round; tanh always inline.
// WRITE: write outputs to op.
// ============================================================
template<int NR, bool WRITE>
__device__ __forceinline__ void ks_run2(const float* __restrict__ xin,
                                        float* __restrict__ op,
                                        float& a,
                                        float (*bsh)[W], float (*ush)[W],
                                        bool act, int i, int im1, int im2,
                                        float d2, float fa2) {
    float xa[2], xb[2];
    #pragma unroll
    for (int q = 0; q < 2; q++) {
        xa[q] = act ? xin[(size_t)(2 * q) * W] : 0.f;
        xb[q] = act ? xin[(size_t)(2 * q + 1) * W] : 0.f;
    }
    #pragma unroll 2
    for (int r = 0; r < NR; r++) {
        float x0 = xa[r & 1], x1 = xb[r & 1];
        if (act && r + 2 < NR) {
            xa[r & 1] = xin[(size_t)(2 * r + 4) * W];
            xb[r & 1] = xin[(size_t)(2 * r + 5) * W];
        }
        float u0 = ftanh2(fa2 * x0);
        float u1 = ftanh2(fa2 * x1);

        float bb = a + u0;
        if (act) { bsh[r & 1][i] = bb; ush[r & 1][i] = u1; }
        __syncthreads();
        if (act) {
            float bm1 = bsh[r & 1][im1], bm2 = bsh[r & 1][im2];
            float u1m1 = ush[r & 1][im1];
            float a1  = d2 * (bb + bm1);
            float a1m = d2 * (bm1 + bm2);
            float a2  = d2 * ((a1 + u1) + (a1m + u1m1));
            if (WRITE) {
                op[(size_t)(2 * r) * W] = a1;
                op[(size_t)(2 * r + 1) * W] = a2;
            }
            a = a2;
        }
    }
}

// ============================================================
// Kernel A <<<195,896>>>: prep (blocks 0..45) + pass1 (46..194)
// pass1 writes ONLY g_dstate (no u-scratch).
// ============================================================
struct SmemKS { float bsh[2][W]; float ush[2][W]; };
struct SmemWT { float xs[898]; float ys[898]; float2 sv[128]; float Pw[7][4]; float cf[10]; };

__global__ void __launch_bounds__(896) ksA(const float* __restrict__ fb,
                                           const float* __restrict__ wavetable,
                                           const float* __restrict__ h,
                                           const float* __restrict__ envp,
                                           const float* __restrict__ lp2) {
    __shared__ union { SmemKS ks; SmemWT wt; } sm;
    int b = blockIdx.x, t = threadIdx.x;

    if (b >= PREPB) {
        int c = b - PREPB;
        int i = t;
        bool act = i < W;
        int im1 = (i == 0) ? (W - 1) : (i - 1);
        int im2 = (i <= 1) ? (i + W - 2) : (i - 2);
        float dec = fminf(fmaxf(h[0] * 0.1f + 0.9f, 0.9f), 0.999f);
        float d2 = dec * 0.5f;
        float fa2 = 2.0f * h[3];

        float a = 0.0f;
        const float* fp = fb + (size_t)c * MCH * W + i;
        if (c < NCH - 1) {
            ks_run2<MCH / 2, false>(fp, nullptr, a, sm.ks.bsh, sm.ks.ush,
                                    act, i, im1, im2, d2, fa2);
            if (act) g_dstate[c * WP + i] = a;
        }
        // chunk 148's zero-init end state is never needed
        return;
    }

    if (b >= 40) {
        if (t < 128) {
            int idx = (b - 40) * 128 + t;
            double decay = (double)h[0] / 10.0 + 0.9;
            decay = fmin(fmax(decay, 0.9), 0.999);
            double ld2 = log(decay * 0.5);
            int m = idx / 512;
            int jj = idx % 512;
            int k = 19 * (m + 1);
            int c0a, wk; kgeomB(k, c0a, wk);
            int m64 = 64 * k;
            float val = 0.0f;
            if (jj < wk) {
                int j = c0a + wk - 1 - jj;
                if (j >= 0 && j <= m64) {
                    double lg = lgamma((double)(m64 + 1)) - lgamma((double)(j + 1))
                              - lgamma((double)(m64 - j + 1)) + (double)m64 * ld2;
                    val = (float)exp(lg);
                }
            }
            g_KtB[idx] = val;
        }
        return;
    }

    if (b >= 2) {
        if (t < 128) {
            int idx = (b - 2) * 128 + t;
            double decay = (double)h[0] / 10.0 + 0.9;
            decay = fmin(fmax(decay, 0.9), 0.999);
            double ld2 = log(decay * 0.5);
            int k = idx / 256 + 1;
            int jj = idx % 256;
            int c0e, wk, jb; kgeom2(k, c0e, wk, jb);
            int m = 64 * k;
            float val = 0.0f;
            if (jj < wk) {
                int j = jb + wk - 1 - jj;
                if (j >= 0 && j <= m) {
                    double lg = lgamma((double)(m + 1)) - lgamma((double)(j + 1))
                              - lgamma((double)(m - j + 1)) + (double)m * ld2;
                    val = (float)exp(lg);
                }
            }
            g_Kt[idx] = val;
        }
        return;
    }

    if (b == 0) {
        if (t >= 1 && t <= GLEN) {
            int c0e, wk, jb; kgeom2(t, c0e, wk, jb);
            g_Kwk[t] = wk;
            g_Koff[t] = AOFF + 1 - c0e - wk;
        }
        if (t >= 22 && t < 28) {
            int m = t - 22;
            int c0a, wk; kgeomB(19 * (m + 1), c0a, wk);
            g_KBwk[m] = wk;
            g_KBc0[m] = c0a;
        }
        if (t != 0) return;

        g_bar = 0;

        double decay = (double)h[0] / 10.0 + 0.9;
        decay = fmin(fmax(decay, 0.9), 0.999);

        double h5 = h[5], h6 = h[6];
        double brf = h5 * SRATE / 4.0; brf = fmin(fmax(brf, 100.0), SRATE / 2.0 - 1.0);
        double brq = fmin(fmax(h6, 0.1), 0.999);
        double w0b = 2.0 * M_PI * brf / SRATE, alb = sin(w0b) / (2.0 * brq), cwb = cos(w0b);
        double a0b = 1.0 + alb;
        double bb0 = 1.0 / a0b, bb1 = (-2.0 * cwb) / a0b;
        double ba1 = (-2.0 * cwb) / a0b, ba2 = (1.0 - alb) / a0b;

        {
            double m00 = -ba1, m01 = -ba2, m10 = 1.0, m11 = 0.0;
            for (int s = 0; s < 5; s++) {                    // -> M^32
                double n00 = m00 * m00 + m01 * m10, n01 = m00 * m01 + m01 * m11;
                double n10 = m10 * m00 + m11 * m10, n11 = m10 * m01 + m11 * m11;
                m00 = n00; m01 = n01; m10 = n10; m11 = n11;
            }
            for (int s = 0; s < 18; s++) {
                g_MsF[s][0] = (float)m00; g_MsF[s][1] = (float)m01;
                g_MsF[s][2] = (float)m10; g_MsF[s][3] = (float)m11;
                double n00 = m00 * m00 + m01 * m10, n01 = m00 * m01 + m01 * m11;
                double n10 = m10 * m00 + m11 * m10, n11 = m10 * m01 + m11 * m11;
                m00 = n00; m01 = n01; m10 = n10; m11 = n11;
            }
        }

        double nD = (double)N_TOT;
        double attack  = 1.0 + (double)envp[0] * 0.1 * nD;
        double release = 1.0 + (double)envp[2] * 0.1 * nD;
        double sustain = fmin(fmax((double)envp[1], 0.0), 1.0);

        g_par[0] = (float)(decay * 0.5);
        g_par[1] = (float)(2.0 * (double)h[3]);
        g_par[2] = (float)bb0; g_par[3] = (float)bb1; g_par[4] = (float)bb0;
        g_par[5] = (float)ba1; g_par[6] = (float)ba2;
        g_par[7] = (float)(1.0 / attack);
        g_par[8] = (float)(1.0 / release);
        g_par[9] = (float)(sustain * (double)h[4]);
        return;
    }

    // ---- b == 1: wavetable prefilter ----
    {
        float* xs = sm.wt.xs; float* ys = sm.wt.ys;
        float2* sv = sm.wt.sv; float (*Pw)[4] = sm.wt.Pw; float* cf = sm.wt.cf;

        if (t < 128)
            for (int p = t; p < 896; p += 128) xs[2 + p] = (p < W) ? wavetable[p] : 0.0f;
        if (t < 2) { xs[t] = 0.0f; ys[t] = 0.0f; }

        if (t == 0) {
            double h1 = h[1], h2 = h[2];
            double lpf = h1 * SRATE / 4.0; lpf = fmin(fmax(lpf, 100.0), SRATE / 2.0 - 1.0);
            double lpq = fmin(fmax(h2, 0.1), 0.999);
            double w0 = 2.0 * M_PI * lpf / SRATE, al = sin(w0) / (2.0 * lpq), cw = cos(w0);
            double a0 = 1.0 + al;
            cf[0] = (float)(((1.0 - cw) * 0.5) / a0);
            cf[1] = (float)((1.0 - cw) / a0);
            cf[2] = cf[0];
            cf[3] = (float)((-2.0 * cw) / a0);
            cf[4] = (float)((1.0 - al) / a0);
            double c2 = 100.0 + (double)lp2[0] * 8000.0;
            double w02 = 2.0 * M_PI * c2 / SRATE, al2 = sin(w02) / (2.0 * 0.707), cw2 = cos(w02);
            double a02 = 1.0 + al2;
            cf[5] = (float)(((1.0 - cw2) * 0.5) / a02);
            cf[6] = (float)((1.0 - cw2) / a02);
            cf[7] = cf[5];
            cf[8] = (float)((-2.0 * cw2) / a02);
            cf[9] = (float)((1.0 - al2) / a02);
        }
        __syncthreads();

        #pragma unroll
        for (int f = 0; f < 2; f++) {
            float b0 = cf[5 * f + 0], b1 = cf[5 * f + 1], b2 = cf[5 * f + 2];
            float a1 = cf[5 * f + 3], a2 = cf[5 * f + 4];
            const float* in = (f == 0) ? xs : ys;
            int base = 2 + 7 * (t & 127);

            if (t < 128) {
                float y1 = 0.f, y2 = 0.f;
                #pragma unroll
                for (int i = 0; i < 7; i++) {
                    float cn = b0 * in[base + i] + b1 * in[base + i - 1] + b2 * in[base + i - 2];
                    float yn = cn - a1 * y1 - a2 * y2;
                    y2 = y1; y1 = yn;
                }
                sv[t] = make_float2(y1, y2);
            }
            if (t == 0) {
                double A00 = -(double)a1, A01 = -(double)a2, A10 = 1.0, A11 = 0.0;
                double q00 = A00*A00 + A01*A10, q01 = A00*A01 + A01*A11;
                double q10 = A10*A00 + A11*A10, q11 = A10*A01 + A11*A11;
                double r00 = q00*q00 + q01*q10, r01 = q00*q01 + q01*q11;
                double r10 = q10*q00 + q11*q10, r11 = q10*q01 + q11*q11;
                double s00 = r00*q00 + r01*q10, s01 = r00*q01 + r01*q11;
                double s10 = r10*q00 + r11*q10, s11 = r10*q01 + r11*q11;
                double m00 = s00*A00 + s01*A10, m01 = s00*A01 + s01*A11;
                double m10 = s10*A00 + s11*A10, m11 = s10*A01 + s11*A11;
                for (int s = 0; s < 7; s++) {
                    Pw[s][0] = (float)m00; Pw[s][1] = (float)m01;
                    Pw[s][2] = (float)m10; Pw[s][3] = (float)m11;
                    double n00 = m00*m00 + m01*m10, n01 = m00*m01 + m01*m11;
                    double n10 = m10*m00 + m11*m10, n11 = m10*m01 + m11*m11;
                    m00 = n00; m01 = n01; m10 = n10; m11 = n11;
                }
            }
            __syncthreads();

            for (int s = 0; s < 7; s++) {
                int off = 1 << s;
                float ax = 0.f, ay = 0.f;
                if (t < 128 && t >= off) {
                    float2 src = sv[t - off];
                    ax = Pw[s][0] * src.x + Pw[s][1] * src.y;
                    ay = Pw[s][2] * src.x + Pw[s][3] * src.y;
                }
                __syncthreads();
                if (t < 128) { sv[t].x += ax; sv[t].y += ay; }
                __syncthreads();
            }

            if (t < 128) {
                float py1 = 0.f, py2 = 0.f;
                if (t > 0) { py1 = sv[t - 1].x; py2 = sv[t - 1].y; }
                #pragma unroll
                for (int i = 0; i < 7; i++) {
                    float cn = b0 * in[base + i] + b1 * in[base + i - 1] + b2 * in[base + i - 2];
                    float yn = cn - a1 * py1 - a2 * py2;
                    py2 = py1; py1 = yn;
                    if (f == 0) ys[base + i] = yn;
                    else { int g = 7 * t + i; if (g < W) g_wt[g] = yn; }
                }
            }
            __syncthreads();
        }
    }
}

// ============================================================
// Kernel B <<<84,256>>>: comb_A (blocks 0..7) + gbar + Bdirect
// ============================================================
__global__ void __launch_bounds__(256) ks_comb() {
    __shared__ union {
        struct { float f[FSZ]; float Ks[256]; } a;
        struct { float f[FB];  float Ks[512]; } b;
    } smc;
    int blk = blockIdx.x, t = threadIdx.x;

    if (blk < NG) {
        float* f  = smc.a.f;
        float* Ks = smc.a.Ks;
        int g = blk;
        for (int p = t; p < g_Kwk[1]; p += 256) Ks[p] = g_Kt[p];
        int wk = g_Kwk[1], off = g_Koff[1];
        int c1 = g * GLEN;
        int len = (g == NG - 1) ? (NCH - (NG - 1) * GLEN) : GLEN;
        int cend  = c1 + len;
        int cendT = (g == NG - 1) ? (NCH - 1) : cend;

        int cbeg;
        if (g == 0) {
            for (int p = t; p < W; p += 256) {
                float v = g_wt[p];
                f_write(f, p, v);
                g_vstart[p] = v;
            }
            cbeg = 1;
        } else {
            for (int p = t; p < W; p += 256) {
                float v = g_dstate[c1 * WP + p];
                f_write(f, p, v);
                g_vstart[(c1 + 1) * WP + p] = v;
            }
            cbeg = c1 + 2;
        }
        __syncthreads();

        int o0 = t * 4;
        bool activ = o0 < W;
        float4 dv = make_float4(0.f, 0.f, 0.f, 0.f);
        if (activ) dv = *(const float4*)(g_dstate + (size_t)(cbeg - 1) * WP + o0);

        for (int c = cbeg; c <= cendT; c++) {
            float4 dnext = make_float4(0.f, 0.f, 0.f, 0.f);
            if (activ && c <= cendT - 1)
                dnext = *(const float4*)(g_dstate + (size_t)c * WP + o0);

            float acc[4] = {dv.x, dv.y, dv.z, dv.w};
            if (activ) conv_into(f, Ks, wk, off, o0, acc);
            __syncthreads();
            if (activ) {
                float* dst;
                if (c < cend) dst = g_vstart + (size_t)c * WP + o0;
                else dst = g_sA + (size_t)(g + 1) * WP + o0;
                #pragma unroll
                for (int e = 0; e < 4; e++) {
                    int p = o0 + e;
                    if (p < W) { f_write(f, p, acc[e]); dst[e] = acc[e]; }
                }
            }
            __syncthreads();
            dv = dnext;
        }
    }
    gbar(NCV * 4);

    {
        float* f  = smc.b.f;
        float* Ks = smc.b.Ks;
        int cid = blk >> 2, q = blk & 3;

        int g = 2;
        #pragma unroll
        for (int gg = 3; gg <= 7; gg++)
            if (cid >= (gg - 2) * (gg - 1) / 2) g = gg;
        int m = cid - (g - 2) * (g - 1) / 2;
        int srcRow = g - m - 1;

        int wk = g_KBwk[m], c0a = g_KBc0[m];
        for (int p = t; p < wk; p += 256) Ks[p] = g_KtB[m * 512 + p];

        for (int p = t; p < W; p += 256) {
            float v = __ldcg(g_sA + (size_t)srcRow * WP + p);
            #pragma unroll
            for (int n = 0; n < 6; n++) {
                int tt = p + n * W;
                if (tt < FB) f[tt] = v;
            }
        }
        __syncthreads();

        int o = q * QOUT + t;
        if (t < QOUT && o < W) {
            float acc = 0.f;
            int base = o - c0a - wk + 1 + LIFT;
            #pragma unroll 4
            for (int jj = 0; jj < wk; jj += 4) {
                float4 k4 = *(const float4*)&Ks[jj];
                acc = fmaf(k4.x, f[base + jj],     acc);
                acc = fmaf(k4.y, f[base + jj + 1], acc);
                acc = fmaf(k4.z, f[base + jj + 2], acc);
                acc = fmaf(k4.w, f[base + jj + 3], acc);
            }
            g_cv[(size_t)cid * WP + o] = acc;
        }
    }
}

// ============================================================
// Kernel C <<<149,896>>>: pass2 (reads fb, recomputes tanh)
// with comb_C correction prologue
// ============================================================
__global__ void __launch_bounds__(896) ksC(const float* __restrict__ fb) {
    __shared__ SmemKS sm;
    __shared__ __align__(16) float f[FSZ];
    __shared__ __align__(16) float Ks[256];
    int c = blockIdx.x, i = threadIdx.x;
    bool act = i < W;
    int im1 = (i == 0) ? (W - 1) : (i - 1);
    int im2 = (i <= 1) ? (i + W - 2) : (i - 2);
    float d2 = g_par[0], fa2 = g_par[1];

    float a;
    if (c < GLEN) {
        a = act ? g_vstart[(size_t)c * WP + i] : 0.0f;
        __syncthreads();
    } else {
        int g = c / GLEN, r = c - g * GLEN;
        for (int p = i; p < W; p += 896) f_write(f, p, xval(g, p));
        int wk = 0, off = 0;
        if (r > 0) {
            wk = g_Kwk[r]; off = g_Koff[r];
            if (i < wk) Ks[i] = g_Kt[(r - 1) * 256 + i];
        }
        __syncthreads();
        if (r == 0) {
            a = act ? f[i + AOFF] : 0.0f;
        } else {
            int o0 = i * 4;
            if (o0 < W) {
                const float* vp = g_vstart + (size_t)c * WP + o0;
                float acc[4] = {vp[0], vp[1], vp[2], vp[3]};
                conv_into(f, Ks, wk, off, o0, acc);
                #pragma unroll
                for (int e = 0; e < 4; e++)
                    if (o0 + e < W) sm.ush[0][o0 + e] = acc[e];
            }
            __syncthreads();
            a = act ? sm.ush[0][i] : 0.0f;
            __syncthreads();
        }
    }

    const float* fp = fb   + (size_t)c * MCH * W + i;
    float*       op = g_ks + (size_t)c * MCH * W + i;

    if (c < NCH - 1) {
        ks_run2<MCH / 2, true>(fp, op, a, sm.bsh, sm.ush, act, i, im1, im2, d2, fa2);
    } else {
        ks_run2<LASTS / 2, true>(fp, op, a, sm.bsh, sm.ush, act, i, im1, im2, d2, fa2);
        __syncthreads();
        if (act) sm.bsh[0][i] = a;
        __syncthreads();
        if (i < REM) {
            float fin = d2 * (sm.bsh[0][i] + sm.bsh[0][im1]);
            int g = NB * W + i;
            if (g >= N_TOT - 256) fin *= (float)(N_TOT - 1 - g) * (1.0f / 255.0f);
            g_ks[g] = fin;
        }
    }
}

// ============================================================
// Band-reject slab machinery, LBQ=32 (stride-33 slab layout)
// ============================================================
__device__ __forceinline__ void bq_load_slab(float* sl, int sb, int w, int l) {
    const float4* gp = (const float4*)(g_ks + (size_t)sb * SPB + (size_t)w * 1024);
    #pragma unroll
    for (int i = 0; i < 8; i++) {
        float4 v = gp[i * 32 + l];
        int s4 = i * 128 + l * 4;
        int c = s4 >> 5, k = s4 & 31;
        float* q = sl + c * 33 + k;
        q[0] = v.x; q[1] = v.y; q[2] = v.z; q[3] = v.w;
    }
}

__device__ __forceinline__ float2 bq_zero_scan(const float* slab, int sb, int t,
                                               int w, int l,
                                               float b0, float b1, float b2,
                                               float a1, float a2,
                                               float& hx1, float& hx2) {
    if (t == 0) {
        size_t s0 = (size_t)sb * SPB;
        hx1 = sb ? g_ks[s0 - 1] : 0.f;
        hx2 = sb ? g_ks[s0 - 2] : 0.f;
    } else {
        int pw = (t - 1) >> 5, pl = (t - 1) & 31;
        const float* pv = slab + pw * SLAB + pl * 33;
        hx1 = pv[31]; hx2 = pv[30];
    }
    const float* cp = slab + w * SLAB + l * 33;
    float x1 = hx1, x2 = hx2, y1 = 0.f, y2 = 0.f;
    #pragma unroll
    for (int k = 0; k < 32; k++) {
        float xn = cp[k];
        float yn = fmaf(b0, xn, fmaf(b1, x1, b2 * x2)) - fmaf(a1, y1, a2 * y2);
        x2 = x1; x1 = xn; y2 = y1; y1 = yn;
    }
    float2 v = make_float2(y1, y2);
    #pragma unroll
    for (int s = 0; s < 5; s++) {
        int off = 1 << s;
        float px = __shfl_up_sync(0xffffffffu, v.x, off);
        float py = __shfl_up_sync(0xffffffffu, v.y, off);
        if (l >= off) {
            float A, B, C, D; mload(s, A, B, C, D);
            v.x = fmaf(A, px, fmaf(B, py, v.x));
            v.y = fmaf(C, px, fmaf(D, py, v.y));
        }
    }
    return v;
}

__global__ void __launch_bounds__(BQTH) bq_passA() {
    __shared__ __align__(16) float slab[BQW * SLAB];
    __shared__ float2 wag[BQW];
    int sb = blockIdx.x, t = threadIdx.x, w = t >> 5, l = t & 31;
    float b0 = g_par[2], b1 = g_par[3], b2 = g_par[4], a1 = g_par[5], a2 = g_par[6];

    bq_load_slab(slab + w * SLAB, sb, w, l);
    __syncthreads();

    float hx1, hx2;
    float2 v = bq_zero_scan(slab, sb, t, w, l, b0, b1, b2, a1, a2, hx1, hx2);
    if (l == 31) wag[w] = v;
    __syncthreads();

    if (t == BQTH - 1) {
        float A, B, C, D; mload(5, A, B, C, D);   // M^1024
        float2 P = wag[0];
        #pragma unroll
        for (int u = 1; u < BQW; u++) {
            float2 nw = wag[u];
            P = make_float2(nw.x + A * P.x + B * P.y, nw.y + C * P.x + D * P.y);
        }
        g_blk[sb] = P;
    }
}

__global__ void __launch_bounds__(BQTH) bq_passB(float* __restrict__ out) {
    __shared__ __align__(16) float slab[BQW * SLAB];
    __shared__ float2 wag[BQW];
    __shared__ float2 tag[BQTH];
    __shared__ float2 bpsh;
    int sb = blockIdx.x, t = threadIdx.x, w = t >> 5, l = t & 31;
    float b0 = g_par[2], b1 = g_par[3], b2 = g_par[4], a1 = g_par[5], a2 = g_par[6];

    // ---- redundant exclusive prefix of 2048 slab aggregates
    {
        float A, B, C, D; mload(7, A, B, C, D);            // M^4096
        float2 Pacc = make_float2(0.f, 0.f);
        const float4* gb = (const float4*)g_blk;
        #pragma unroll
        for (int j = 0; j < 8; j++) {
            float4 q2 = gb[t * 8 + j];
            Pacc = make_float2(q2.x + A * Pacc.x + B * Pacc.y,
                               q2.y + C * Pacc.x + D * Pacc.y);
            Pacc = make_float2(q2.z + A * Pacc.x + B * Pacc.y,
                               q2.w + C * Pacc.x + D * Pacc.y);
        }
        tag[t] = Pacc;
    }
    __syncthreads();
    for (int s = 0; s < 7; s++) {
        int off = 1 << s;
        float E0, E1, E2, E3; mload(11 + s, E0, E1, E2, E3);
        float ax = 0.f, ay = 0.f;
        if (t >= off) {
            float2 src = tag[t - off];
            ax = fmaf(E0, src.x, E1 * src.y);
            ay = fmaf(E2, src.x, E3 * src.y);
        }
        __syncthreads();
        tag[t].x += ax; tag[t].y += ay;
        __syncthreads();
    }
    if (t == (sb >> 4)) {
        float A, B, C, D; mload(7, A, B, C, D);
        float2 cur = t ? tag[t - 1] : make_float2(0.f, 0.f);
        int r = sb & 15;
        for (int e = 0; e < r; e++) {
            float2 lv = g_blk[t * 16 + e];
            cur = make_float2(lv.x + A * cur.x + B * cur.y,
                              lv.y + C * cur.x + D * cur.y);
        }
        bpsh = cur;
    }

    bq_load_slab(slab + w * SLAB, sb, w, l);
    __syncthreads();

    float hx1, hx2;
    float2 v = bq_zero_scan(slab, sb, t, w, l, b0, b1, b2, a1, a2, hx1, hx2);
    if (l == 31) wag[w] = v;
    __syncthreads();

    float2 P = make_float2(0.f, 0.f);
    {
        float A, B, C, D; mload(5, A, B, C, D);
        for (int u = 0; u < w; u++) {
            float2 nw = wag[u];
            P = make_float2(nw.x + A * P.x + B * P.y, nw.y + C * P.x + D * P.y);
        }
    }
    float ex = __shfl_up_sync(0xffffffffu, v.x, 1);
    float ey = __shfl_up_sync(0xffffffffu, v.y, 1);
    if (l == 0) { ex = 0.f; ey = 0.f; }
    {
        float ra, rb, rc, rd; mpow32(l, ra, rb, rc, rd);
        ex += ra * P.x + rb * P.y;
        ey += rc * P.x + rd * P.y;
    }
    {
        float2 Pb = bpsh;
        float ra, rb, rc, rd; mpow32(t, ra, rb, rc, rd);
        ex += ra * Pb.x + rb * Pb.y;
        ey += rc * Pb.x + rd * Pb.y;
    }

    {
        float ia = g_par[7], ir = g_par[8], sg = g_par[9];
        float* cp = slab + w * SLAB + l * 33;
        float x1 = hx1, x2 = hx2, y1 = ex, y2 = ey;
        size_t s0 = (size_t)sb * SPB + (size_t)t * 32;
        #pragma unroll
        for (int k = 0; k < 32; k++) {
            float xn = cp[k];
            float yn = fmaf(b0, xn, fmaf(b1, x1, b2 * x2)) - fmaf(a1, y1, a2 * y2);
            x2 = x1; x1 = xn; y2 = y1; y1 = yn;
            float fn = (float)(s0 + k);
            float e1 = fminf(fn * ia, 1.0f);
            float e2 = fminf(((float)(N_TOT - 1) - fn) * ir, 1.0f);
            cp[k] = yn * e1 * e2 * sg;
        }
    }
    __syncwarp();

    {
        const float* sl = slab + w * SLAB;
        float4* op = (float4*)(out + (size_t)sb * SPB + (size_t)w * 1024);
        #pragma unroll
        for (int i = 0; i < 8; i++) {
            int s4 = i * 128 + l * 4;
            int c = s4 >> 5, k = s4 & 31;
            const float* q = sl + c * 33 + k;
            op[i * 32 + l] = make_float4(q[0], q[1], q[2], q[3]);
        }
    }
}

// ============================================================
extern "C" void kernel_launch(void* const* d_in, const int* in_sizes, int n_in,
                              void* d_out, int out_size) {
    const float* fb  = (const float*)d_in[0];
    const float* wt  = (const float*)d_in[1];
    const float* h   = (const float*)d_in[2];
    const float* ep  = (const float*)d_in[3];
    const float* lp2 = (const float*)d_in[4];
    float* out = (float*)d_out;

    ksA<<<PREPB + NCH - 1, 896>>>(fb, wt, h, ep, lp2);   // prep + pass1 (no u-scratch)
    ks_comb<<<NCV * 4, 256>>>();                          // comb_A + gbar + Bdirect
    ksC<<<NCH, 896>>>(fb);                                // comb_C prologue + pass2
    bq_passA<<<NBQB, BQTH>>>();
    bq_passB<<<NBQB, BQTH>>>(out);                        // fused scan + replay
}